// round 1
// baseline (speedup 1.0000x reference)
#include <cuda_runtime.h>

#define N_NODES 100000
#define N_EDGES 1600000
#define DIM 128
#define HID 256

// ---------------- scratch (static device globals; no allocs allowed) --------
__device__ float g_deg[N_NODES];
__device__ float g_coef[N_EDGES];
__device__ float g_ha[N_NODES * DIM];
__device__ float g_hb[N_NODES * DIM];
__device__ float g_hid[N_NODES * HID];
__device__ int   g_sh;   // 0: indices are int32, 1: indices are int64 (read low word)

// ---------------- small utility kernels ------------------------------------
__global__ void detect_kernel(const int* __restrict__ src) {
    // src starts with arange(N): int32 -> src32[1]==1 ; int64 -> src32[1]==0, src32[2]==1
    if (blockIdx.x == 0 && threadIdx.x == 0)
        g_sh = (src[1] == 0 && src[2] == 1) ? 1 : 0;
}

__global__ void zero_kernel(float* __restrict__ p, int n4) {
    int i = blockIdx.x * blockDim.x + threadIdx.x;
    if (i < n4) ((float4*)p)[i] = make_float4(0.f, 0.f, 0.f, 0.f);
}

// ---------------- degree + norm coefficients -------------------------------
__global__ void deg_kernel(const int* __restrict__ src) {
    int e = blockIdx.x * blockDim.x + threadIdx.x;
    if (e < N_EDGES) {
        int sh = g_sh;
        int s = src[(long)e << sh];
        atomicAdd(&g_deg[s], 1.0f);
    }
}

__global__ void coef_kernel(const int* __restrict__ src, const int* __restrict__ dst) {
    int e = blockIdx.x * blockDim.x + threadIdx.x;
    if (e < N_EDGES) {
        int sh = g_sh;
        float ds = g_deg[src[(long)e << sh]];
        float dd = g_deg[dst[(long)e << sh]];
        g_coef[e] = rsqrtf(ds * dd);
    }
}

// ---------------- bundle rotations ------------------------------------------
// out[n, b*16+c*4+e] = sum_d rep[n,b,c,d] * x[n, b*16+d*4+e]
__global__ void rot_kernel(const float* __restrict__ x, const float* __restrict__ rep,
                           float* __restrict__ out) {
    int i = blockIdx.x * blockDim.x + threadIdx.x;   // < N_NODES*DIM
    int n = i >> 7;
    int t = i & 127;
    int b = t >> 4, c = (t >> 2) & 3, el = t & 3;
    float4 r = *(const float4*)(rep + (((long)n * 8 + b) * 16 + c * 4));
    const float* xb = x + (long)n * DIM + b * 16 + el;
    out[i] = r.x * xb[0] + r.y * xb[4] + r.z * xb[8] + r.w * xb[12];
}

// out[n, b*16+c*4+e] = sum_d rep[n,b,d,c] * h[n, b*16+d*4+e]   (transposed rep)
__global__ void rot_t_kernel(const float* __restrict__ h, const float* __restrict__ rep,
                             float* __restrict__ out) {
    int i = blockIdx.x * blockDim.x + threadIdx.x;
    int n = i >> 7;
    int t = i & 127;
    int b = t >> 4, c = (t >> 2) & 3, el = t & 3;
    const float* rb = rep + (((long)n * 8 + b) * 16 + c);
    const float* hb = h + (long)n * DIM + b * 16 + el;
    out[i] = rb[0] * hb[0] + rb[4] * hb[4] + rb[8] * hb[8] + rb[12] * hb[12];
}

// ---------------- edge scatter: hout[dst] += hin[src] * coef ----------------
// One warp per edge, float4 per lane, vector red.add.v4.f32 atomics.
__global__ void scatter_kernel(const float* __restrict__ hin, float* __restrict__ hout,
                               const int* __restrict__ src, const int* __restrict__ dst,
                               const float* __restrict__ coef) {
    int gid = blockIdx.x * blockDim.x + threadIdx.x;
    int e = gid >> 5;
    int lane = gid & 31;
    int sh = g_sh;
    long s = (long)src[(long)e << sh];
    long d = (long)dst[(long)e << sh];
    float cf = coef[e];
    float4 v = *(const float4*)(hin + s * DIM + lane * 4);
    float* dp = hout + d * DIM + lane * 4;
    unsigned long long gp = (unsigned long long)__cvta_generic_to_global(dp);
    asm volatile("red.global.add.v4.f32 [%0], {%1,%2,%3,%4};"
                 :: "l"(gp), "f"(v.x * cf), "f"(v.y * cf), "f"(v.z * cf), "f"(v.w * cf)
                 : "memory");
}

// ---------------- FFN layer 1: hid = gelu(h @ w1^T + b1) --------------------
// Block: 256 threads, 32 nodes. w1 cached in SMEM padded to 132 floats/row
// (bank-stride 4 -> conflict-free LDS.128 in quarter-warp phases).
__global__ void ffn1_kernel(const float* __restrict__ hin, const float* __restrict__ w1,
                            const float* __restrict__ b1, float* __restrict__ hid) {
    extern __shared__ float sm[];
    float* s_w = sm;               // 256 x 132
    float* s_h = sm + 256 * 132;   // 32 x 128
    int tid = threadIdx.x;
    for (int idx = tid; idx < HID * DIM; idx += 256) {
        int j = idx >> 7, k = idx & 127;
        s_w[j * 132 + k] = w1[idx];
    }
    long nbase = (long)blockIdx.x * 32;
    for (int idx = tid; idx < 32 * DIM; idx += 256)
        s_h[idx] = hin[nbase * DIM + idx];
    float bj = b1[tid];
    __syncthreads();

    const float4* wr = (const float4*)(s_w + tid * 132);
    for (int g = 0; g < 32; g++) {
        const float4* hr = (const float4*)(s_h + g * DIM);
        float a0 = 0.f, a1 = 0.f, a2 = 0.f, a3 = 0.f;
#pragma unroll
        for (int kk = 0; kk < 32; kk++) {
            float4 w = wr[kk];
            float4 h = hr[kk];
            a0 += w.x * h.x; a1 += w.y * h.y; a2 += w.z * h.z; a3 += w.w * h.w;
        }
        float a = (a0 + a1) + (a2 + a3) + bj;
        // exact GELU: 0.5*x*(1+erf(x/sqrt(2)))
        hid[(nbase + g) * HID + tid] = 0.5f * a * (1.0f + erff(a * 0.7071067811865476f));
    }
}

// ---------------- FFN layer 2: out = hid @ w2^T + b2 ------------------------
// Block: 256 threads, 16 nodes. Threads split into 2 halves over nodes.
__global__ void ffn2_kernel(const float* __restrict__ hid, const float* __restrict__ w2,
                            const float* __restrict__ b2, float* __restrict__ out) {
    extern __shared__ float sm[];
    float* s_w = sm;               // 128 x 260
    float* s_h = sm + 128 * 260;   // 16 x 256
    int tid = threadIdx.x;
    for (int idx = tid; idx < DIM * HID; idx += 256) {
        int j = idx >> 8, k = idx & 255;
        s_w[j * 260 + k] = w2[idx];
    }
    long nbase = (long)blockIdx.x * 16;
    for (int idx = tid; idx < 16 * HID; idx += 256)
        s_h[idx] = hid[nbase * HID + idx];
    __syncthreads();

    int j = tid & 127, half = tid >> 7;
    float bj = b2[j];
    const float4* wr = (const float4*)(s_w + j * 260);
    for (int g = half; g < 16; g += 2) {
        const float4* hr = (const float4*)(s_h + g * HID);
        float a0 = 0.f, a1 = 0.f, a2 = 0.f, a3 = 0.f;
#pragma unroll
        for (int kk = 0; kk < 64; kk++) {
            float4 w = wr[kk];
            float4 h = hr[kk];
            a0 += w.x * h.x; a1 += w.y * h.y; a2 += w.z * h.z; a3 += w.w * h.w;
        }
        out[(nbase + g) * DIM + j] = (a0 + a1) + (a2 + a3) + bj;
    }
}

// ---------------- launch ----------------------------------------------------
extern "C" void kernel_launch(void* const* d_in, const int* in_sizes, int n_in,
                              void* d_out, int out_size) {
    const float* x   = (const float*)d_in[0];
    const float* rep = (const float*)d_in[1];
    const int*   src = (const int*)d_in[2];
    const int*   dst = (const int*)d_in[3];
    const float* w1  = (const float*)d_in[4];
    const float* b1  = (const float*)d_in[5];
    const float* w2  = (const float*)d_in[6];
    const float* b2  = (const float*)d_in[7];
    float* out = (float*)d_out;

    cudaFuncSetAttribute(ffn1_kernel, cudaFuncAttributeMaxDynamicSharedMemorySize,
                         (256 * 132 + 32 * 128) * 4);
    cudaFuncSetAttribute(ffn2_kernel, cudaFuncAttributeMaxDynamicSharedMemorySize,
                         (128 * 260 + 16 * 256) * 4);

    float *ha, *hb, *hidp, *degp, *coefp;
    cudaGetSymbolAddress((void**)&ha,   g_ha);
    cudaGetSymbolAddress((void**)&hb,   g_hb);
    cudaGetSymbolAddress((void**)&hidp, g_hid);
    cudaGetSymbolAddress((void**)&degp, g_deg);
    cudaGetSymbolAddress((void**)&coefp, g_coef);

    detect_kernel<<<1, 1>>>(src);

    // degrees + norm coefs
    zero_kernel<<<(N_NODES / 4 + 255) / 256, 256>>>(degp, N_NODES / 4);
    deg_kernel<<<N_EDGES / 256, 256>>>(src);
    coef_kernel<<<N_EDGES / 256, 256>>>(src, dst);

    // forward rotation: x -> ha
    rot_kernel<<<(N_NODES * DIM) / 256, 256>>>(x, rep, ha);

    // message passing step 1: ha -> hb
    zero_kernel<<<(N_NODES * DIM / 4) / 256, 256>>>(hb, N_NODES * DIM / 4);
    scatter_kernel<<<(N_EDGES * 32) / 256, 256>>>(ha, hb, src, dst, coefp);

    // message passing step 2: hb -> ha
    zero_kernel<<<(N_NODES * DIM / 4) / 256, 256>>>(ha, N_NODES * DIM / 4);
    scatter_kernel<<<(N_EDGES * 32) / 256, 256>>>(hb, ha, src, dst, coefp);

    // inverse rotation: ha -> hb
    rot_t_kernel<<<(N_NODES * DIM) / 256, 256>>>(ha, rep, hb);

    // FFN
    ffn1_kernel<<<N_NODES / 32, 256, (256 * 132 + 32 * 128) * 4>>>(hb, w1, b1, hidp);
    ffn2_kernel<<<N_NODES / 16, 256, (128 * 260 + 16 * 256) * 4>>>(hidp, w2, b2, out);
}

// round 2
// speedup vs baseline: 1.9459x; 1.9459x over previous
#include <cuda_runtime.h>

#define N_NODES 100000
#define N_EDGES 1600000
#define DIM 128
#define HID 256

// ---------------- scratch (static device globals; no allocs allowed) --------
__device__ float g_deg[N_NODES];
__device__ float g_coef[N_EDGES];
__device__ float g_ha[N_NODES * DIM];
__device__ float g_hb[N_NODES * DIM];
__device__ float g_hid[N_NODES * HID];
__device__ int   g_sh;   // 0: indices are int32, 1: int64 (read low word)

// ---------------- small utility kernels ------------------------------------
__global__ void detect_kernel(const int* __restrict__ src) {
    if (blockIdx.x == 0 && threadIdx.x == 0)
        g_sh = (src[1] == 0 && src[2] == 1) ? 1 : 0;
}

__global__ void zero_kernel(float* __restrict__ p, int n4) {
    int i = blockIdx.x * blockDim.x + threadIdx.x;
    if (i < n4) ((float4*)p)[i] = make_float4(0.f, 0.f, 0.f, 0.f);
}

// ---------------- degree + norm coefficients -------------------------------
__global__ void deg_kernel(const int* __restrict__ src) {
    int e = blockIdx.x * blockDim.x + threadIdx.x;
    if (e < N_EDGES) {
        int sh = g_sh;
        atomicAdd(&g_deg[src[(long)e << sh]], 1.0f);
    }
}

__global__ void coef_kernel(const int* __restrict__ src, const int* __restrict__ dst) {
    int e = blockIdx.x * blockDim.x + threadIdx.x;
    if (e < N_EDGES) {
        int sh = g_sh;
        float ds = g_deg[src[(long)e << sh]];
        float dd = g_deg[dst[(long)e << sh]];
        g_coef[e] = rsqrtf(ds * dd);
    }
}

// ---------------- bundle rotations ------------------------------------------
__global__ void rot_kernel(const float* __restrict__ x, const float* __restrict__ rep,
                           float* __restrict__ out) {
    int i = blockIdx.x * blockDim.x + threadIdx.x;
    int n = i >> 7;
    int t = i & 127;
    int b = t >> 4, c = (t >> 2) & 3, el = t & 3;
    float4 r = *(const float4*)(rep + (((long)n * 8 + b) * 16 + c * 4));
    const float* xb = x + (long)n * DIM + b * 16 + el;
    out[i] = r.x * xb[0] + r.y * xb[4] + r.z * xb[8] + r.w * xb[12];
}

__global__ void rot_t_kernel(const float* __restrict__ h, const float* __restrict__ rep,
                             float* __restrict__ out) {
    int i = blockIdx.x * blockDim.x + threadIdx.x;
    int n = i >> 7;
    int t = i & 127;
    int b = t >> 4, c = (t >> 2) & 3, el = t & 3;
    const float* rb = rep + (((long)n * 8 + b) * 16 + c);
    const float* hb = h + (long)n * DIM + b * 16 + el;
    out[i] = rb[0] * hb[0] + rb[4] * hb[4] + rb[8] * hb[8] + rb[12] * hb[12];
}

// ---------------- edge scatter: hout[dst] += hin[src] * coef ----------------
__global__ void scatter_kernel(const float* __restrict__ hin, float* __restrict__ hout,
                               const int* __restrict__ src, const int* __restrict__ dst,
                               const float* __restrict__ coef) {
    int gid = blockIdx.x * blockDim.x + threadIdx.x;
    int e = gid >> 5;
    int lane = gid & 31;
    int sh = g_sh;
    long s = (long)src[(long)e << sh];
    long d = (long)dst[(long)e << sh];
    float cf = coef[e];
    float4 v = *(const float4*)(hin + s * DIM + lane * 4);
    float* dp = hout + d * DIM + lane * 4;
    unsigned long long gp = (unsigned long long)__cvta_generic_to_global(dp);
    asm volatile("red.global.add.v4.f32 [%0], {%1,%2,%3,%4};"
                 :: "l"(gp), "f"(v.x * cf), "f"(v.y * cf), "f"(v.z * cf), "f"(v.w * cf)
                 : "memory");
}

// ---------------- FFN layer 1: hid = gelu(h @ w1^T + b1) --------------------
// Register-tiled GEMM: block = 256 threads (jt in [0,32), gt in [0,8)).
// Block tile: 32 nodes x 128 hidden (blockIdx.y selects hidden half).
// Thread tile: 4 g x 4 j with j strided by 32 (conflict-free LDS.128).
#define SW1 (DIM + 4)    // 132
__global__ void __launch_bounds__(256) ffn1_kernel(
        const float* __restrict__ hin, const float* __restrict__ w1,
        const float* __restrict__ b1, float* __restrict__ hid) {
    extern __shared__ float sm[];
    float* s_w = sm;                 // 128 x SW1
    float* s_h = sm + 128 * SW1;     // 32 x SW1
    int tid = threadIdx.x;
    int jhalf = blockIdx.y;          // 0 or 1
    long nbase = (long)blockIdx.x * 32;

    // load w half: 128 j-rows x 128 k, as float4
    const float4* wg = (const float4*)(w1 + (long)jhalf * 128 * DIM);
    for (int idx = tid; idx < 128 * 32; idx += 256) {
        int j = idx >> 5, kq = idx & 31;
        *(float4*)&s_w[j * SW1 + kq * 4] = wg[idx];
    }
    // load h tile: 32 g-rows x 128 k
    const float4* hg = (const float4*)(hin + nbase * DIM);
    for (int idx = tid; idx < 32 * 32; idx += 256) {
        int g = idx >> 5, kq = idx & 31;
        *(float4*)&s_h[g * SW1 + kq * 4] = hg[idx];
    }
    __syncthreads();

    int jt = tid & 31;
    int g0 = (tid >> 5) * 4;

    float acc[4][4];
#pragma unroll
    for (int a = 0; a < 4; a++)
#pragma unroll
        for (int b = 0; b < 4; b++) acc[a][b] = 0.f;

    const float* hp = s_h + g0 * SW1;
    const float* wp = s_w + jt * SW1;

#pragma unroll 4
    for (int k = 0; k < DIM; k += 4) {
        float4 h4[4], w4[4];
#pragma unroll
        for (int gg = 0; gg < 4; gg++) h4[gg] = *(const float4*)(hp + gg * SW1 + k);
#pragma unroll
        for (int jj = 0; jj < 4; jj++) w4[jj] = *(const float4*)(wp + jj * 32 * SW1 + k);
#pragma unroll
        for (int gg = 0; gg < 4; gg++)
#pragma unroll
            for (int jj = 0; jj < 4; jj++) {
                acc[gg][jj] += h4[gg].x * w4[jj].x;
                acc[gg][jj] += h4[gg].y * w4[jj].y;
                acc[gg][jj] += h4[gg].z * w4[jj].z;
                acc[gg][jj] += h4[gg].w * w4[jj].w;
            }
    }

#pragma unroll
    for (int jj = 0; jj < 4; jj++) {
        int j = jhalf * 128 + jj * 32 + jt;
        float bj = b1[j];
#pragma unroll
        for (int gg = 0; gg < 4; gg++) {
            float a = acc[gg][jj] + bj;
            float ge = 0.5f * a * (1.0f + erff(a * 0.7071067811865476f));
            hid[(nbase + g0 + gg) * HID + j] = ge;
        }
    }
}

// ---------------- FFN layer 2: out = hid @ w2^T + b2 ------------------------
// Block tile: 32 nodes x 128 out, K=256. Same register tiling.
#define SW2 (HID + 4)    // 260
__global__ void __launch_bounds__(256) ffn2_kernel(
        const float* __restrict__ hidp, const float* __restrict__ w2,
        const float* __restrict__ b2, float* __restrict__ out) {
    extern __shared__ float sm[];
    float* s_w = sm;                 // 128 x SW2
    float* s_h = sm + 128 * SW2;     // 32 x SW2
    int tid = threadIdx.x;
    long nbase = (long)blockIdx.x * 32;

    const float4* wg = (const float4*)w2;
    for (int idx = tid; idx < 128 * 64; idx += 256) {
        int j = idx >> 6, kq = idx & 63;
        *(float4*)&s_w[j * SW2 + kq * 4] = wg[idx];
    }
    const float4* hg = (const float4*)(hidp + nbase * HID);
    for (int idx = tid; idx < 32 * 64; idx += 256) {
        int g = idx >> 6, kq = idx & 63;
        *(float4*)&s_h[g * SW2 + kq * 4] = hg[idx];
    }
    __syncthreads();

    int jt = tid & 31;
    int g0 = (tid >> 5) * 4;

    float acc[4][4];
#pragma unroll
    for (int a = 0; a < 4; a++)
#pragma unroll
        for (int b = 0; b < 4; b++) acc[a][b] = 0.f;

    const float* hp = s_h + g0 * SW2;
    const float* wp = s_w + jt * SW2;

#pragma unroll 4
    for (int k = 0; k < HID; k += 4) {
        float4 h4[4], w4[4];
#pragma unroll
        for (int gg = 0; gg < 4; gg++) h4[gg] = *(const float4*)(hp + gg * SW2 + k);
#pragma unroll
        for (int jj = 0; jj < 4; jj++) w4[jj] = *(const float4*)(wp + jj * 32 * SW2 + k);
#pragma unroll
        for (int gg = 0; gg < 4; gg++)
#pragma unroll
            for (int jj = 0; jj < 4; jj++) {
                acc[gg][jj] += h4[gg].x * w4[jj].x;
                acc[gg][jj] += h4[gg].y * w4[jj].y;
                acc[gg][jj] += h4[gg].z * w4[jj].z;
                acc[gg][jj] += h4[gg].w * w4[jj].w;
            }
    }

#pragma unroll
    for (int jj = 0; jj < 4; jj++) {
        int j = jj * 32 + jt;
        float bj = b2[j];
#pragma unroll
        for (int gg = 0; gg < 4; gg++)
            out[(nbase + g0 + gg) * DIM + j] = acc[gg][jj] + bj;
    }
}

// ---------------- launch ----------------------------------------------------
extern "C" void kernel_launch(void* const* d_in, const int* in_sizes, int n_in,
                              void* d_out, int out_size) {
    const float* x   = (const float*)d_in[0];
    const float* rep = (const float*)d_in[1];
    const int*   src = (const int*)d_in[2];
    const int*   dst = (const int*)d_in[3];
    const float* w1  = (const float*)d_in[4];
    const float* b1  = (const float*)d_in[5];
    const float* w2  = (const float*)d_in[6];
    const float* b2  = (const float*)d_in[7];
    float* out = (float*)d_out;

    static int smem_set = 0;
    int smem1 = (128 * SW1 + 32 * SW1) * 4;   // 84,480 B
    int smem2 = (128 * SW2 + 32 * SW2) * 4;   // 166,400 B
    if (!smem_set) {
        cudaFuncSetAttribute(ffn1_kernel, cudaFuncAttributeMaxDynamicSharedMemorySize, smem1);
        cudaFuncSetAttribute(ffn2_kernel, cudaFuncAttributeMaxDynamicSharedMemorySize, smem2);
        smem_set = 1;
    }

    float *ha, *hb, *hidp, *degp, *coefp;
    cudaGetSymbolAddress((void**)&ha,   g_ha);
    cudaGetSymbolAddress((void**)&hb,   g_hb);
    cudaGetSymbolAddress((void**)&hidp, g_hid);
    cudaGetSymbolAddress((void**)&degp, g_deg);
    cudaGetSymbolAddress((void**)&coefp, g_coef);

    detect_kernel<<<1, 1>>>(src);

    zero_kernel<<<(N_NODES / 4 + 255) / 256, 256>>>(degp, N_NODES / 4);
    deg_kernel<<<N_EDGES / 256, 256>>>(src);
    coef_kernel<<<N_EDGES / 256, 256>>>(src, dst);

    rot_kernel<<<(N_NODES * DIM) / 256, 256>>>(x, rep, ha);

    zero_kernel<<<(N_NODES * DIM / 4) / 256, 256>>>(hb, N_NODES * DIM / 4);
    scatter_kernel<<<(N_EDGES * 32) / 256, 256>>>(ha, hb, src, dst, coefp);

    zero_kernel<<<(N_NODES * DIM / 4) / 256, 256>>>(ha, N_NODES * DIM / 4);
    scatter_kernel<<<(N_EDGES * 32) / 256, 256>>>(hb, ha, src, dst, coefp);

    rot_t_kernel<<<(N_NODES * DIM) / 256, 256>>>(ha, rep, hb);

    dim3 g1(N_NODES / 32, 2);
    ffn1_kernel<<<g1, 256, smem1>>>(hb, w1, b1, hidp);
    ffn2_kernel<<<N_NODES / 32, 256, smem2>>>(hidp, w2, b2, out);
}

// round 3
// speedup vs baseline: 2.0737x; 1.0657x over previous
#include <cuda_runtime.h>

#define N_NODES 100000
#define N_EDGES 1600000
#define DIM 128
#define HID 256

typedef unsigned long long u64;

// ---------------- scratch (static device globals; no allocs allowed) --------
__device__ float g_deg[N_NODES];
__device__ float g_coef[N_EDGES];
__device__ float g_ha[N_NODES * DIM];
__device__ float g_hb[N_NODES * DIM];
__device__ float g_hc[N_NODES * DIM];
__device__ float g_hid[N_NODES * HID];
__device__ int   g_sh;   // 0: indices are int32, 1: int64 (read low word)

// packed f32x2 FMA (Blackwell): d = a*b + c elementwise on 2 packed floats
__device__ __forceinline__ u64 ffma2(u64 a, u64 b, u64 c) {
    u64 d;
    asm("fma.rn.f32x2 %0, %1, %2, %3;" : "=l"(d) : "l"(a), "l"(b), "l"(c));
    return d;
}

// ---------------- small utility kernels ------------------------------------
__global__ void detect_kernel(const int* __restrict__ src) {
    if (blockIdx.x == 0 && threadIdx.x == 0)
        g_sh = (src[1] == 0 && src[2] == 1) ? 1 : 0;
}

__global__ void zero_kernel(float* __restrict__ p, int n4) {
    int i = blockIdx.x * blockDim.x + threadIdx.x;
    if (i < n4) ((float4*)p)[i] = make_float4(0.f, 0.f, 0.f, 0.f);
}

// ---------------- degree + norm coefficients -------------------------------
__global__ void deg_kernel(const int* __restrict__ src) {
    int e = blockIdx.x * blockDim.x + threadIdx.x;
    if (e < N_EDGES) {
        int sh = g_sh;
        atomicAdd(&g_deg[src[(long)e << sh]], 1.0f);
    }
}

__global__ void coef_kernel(const int* __restrict__ src, const int* __restrict__ dst) {
    int e = blockIdx.x * blockDim.x + threadIdx.x;
    if (e < N_EDGES) {
        int sh = g_sh;
        float ds = g_deg[src[(long)e << sh]];
        float dd = g_deg[dst[(long)e << sh]];
        g_coef[e] = rsqrtf(ds * dd);
    }
}

// ---------------- forward rotation + zero both scatter targets --------------
__global__ void rot_kernel(const float* __restrict__ x, const float* __restrict__ rep,
                           float* __restrict__ out,
                           float* __restrict__ z1, float* __restrict__ z2) {
    int i = blockIdx.x * blockDim.x + threadIdx.x;
    int n = i >> 7;
    int t = i & 127;
    int b = t >> 4, c = (t >> 2) & 3, el = t & 3;
    float4 r = *(const float4*)(rep + (((long)n * 8 + b) * 16 + c * 4));
    const float* xb = x + (long)n * DIM + b * 16 + el;
    out[i] = r.x * xb[0] + r.y * xb[4] + r.z * xb[8] + r.w * xb[12];
    z1[i] = 0.f;
    z2[i] = 0.f;
}

__global__ void rot_t_kernel(const float* __restrict__ h, const float* __restrict__ rep,
                             float* __restrict__ out) {
    int i = blockIdx.x * blockDim.x + threadIdx.x;
    int n = i >> 7;
    int t = i & 127;
    int b = t >> 4, c = (t >> 2) & 3, el = t & 3;
    const float* rb = rep + (((long)n * 8 + b) * 16 + c);
    const float* hb = h + (long)n * DIM + b * 16 + el;
    out[i] = rb[0] * hb[0] + rb[4] * hb[4] + rb[8] * hb[8] + rb[12] * hb[12];
}

// ---------------- edge scatter: hout[dst] += hin[src] * coef ----------------
__global__ void scatter_kernel(const float* __restrict__ hin, float* __restrict__ hout,
                               const int* __restrict__ src, const int* __restrict__ dst,
                               const float* __restrict__ coef) {
    int gid = blockIdx.x * blockDim.x + threadIdx.x;
    int e = gid >> 5;
    int lane = gid & 31;
    int sh = g_sh;
    long s = (long)__ldg(&src[(long)e << sh]);
    long d = (long)__ldg(&dst[(long)e << sh]);
    float cf = __ldg(&coef[e]);
    float4 v = __ldg((const float4*)(hin + s * DIM + lane * 4));
    float* dp = hout + d * DIM + lane * 4;
    unsigned long long gp = (unsigned long long)__cvta_generic_to_global(dp);
    asm volatile("red.global.add.v4.f32 [%0], {%1,%2,%3,%4};"
                 :: "l"(gp), "f"(v.x * cf), "f"(v.y * cf), "f"(v.z * cf), "f"(v.w * cf)
                 : "memory");
}

// ---------------- FFN layer 1: hid = gelu(h @ w1^T + b1) --------------------
// Register-tiled GEMM with packed f32x2 FFMA. Block = 256 thr, tile 32g x 128j.
#define SW1 (DIM + 4)    // 132
__global__ void __launch_bounds__(256) ffn1_kernel(
        const float* __restrict__ hin, const float* __restrict__ w1,
        const float* __restrict__ b1, float* __restrict__ hid) {
    extern __shared__ float sm[];
    float* s_w = sm;                 // 128 x SW1
    float* s_h = sm + 128 * SW1;     // 32 x SW1
    int tid = threadIdx.x;
    int jhalf = blockIdx.y;
    long nbase = (long)blockIdx.x * 32;

    const float4* wg = (const float4*)(w1 + (long)jhalf * 128 * DIM);
    for (int idx = tid; idx < 128 * 32; idx += 256) {
        int j = idx >> 5, kq = idx & 31;
        *(float4*)&s_w[j * SW1 + kq * 4] = wg[idx];
    }
    const float4* hg = (const float4*)(hin + nbase * DIM);
    for (int idx = tid; idx < 32 * 32; idx += 256) {
        int g = idx >> 5, kq = idx & 31;
        *(float4*)&s_h[g * SW1 + kq * 4] = hg[idx];
    }
    __syncthreads();

    int jt = tid & 31;
    int g0 = (tid >> 5) * 4;

    u64 acc[4][4];
#pragma unroll
    for (int a = 0; a < 4; a++)
#pragma unroll
        for (int b = 0; b < 4; b++) acc[a][b] = 0ull;

    const float* hp = s_h + g0 * SW1;
    const float* wp = s_w + jt * SW1;

#pragma unroll 4
    for (int k = 0; k < DIM; k += 4) {
        float4 h4[4], w4[4];
#pragma unroll
        for (int gg = 0; gg < 4; gg++) h4[gg] = *(const float4*)(hp + gg * SW1 + k);
#pragma unroll
        for (int jj = 0; jj < 4; jj++) w4[jj] = *(const float4*)(wp + jj * 32 * SW1 + k);
#pragma unroll
        for (int gg = 0; gg < 4; gg++) {
            u64 h01 = ((const u64*)&h4[gg])[0];
            u64 h23 = ((const u64*)&h4[gg])[1];
#pragma unroll
            for (int jj = 0; jj < 4; jj++) {
                u64 w01 = ((const u64*)&w4[jj])[0];
                u64 w23 = ((const u64*)&w4[jj])[1];
                acc[gg][jj] = ffma2(h01, w01, acc[gg][jj]);
                acc[gg][jj] = ffma2(h23, w23, acc[gg][jj]);
            }
        }
    }

#pragma unroll
    for (int jj = 0; jj < 4; jj++) {
        int j = jhalf * 128 + jj * 32 + jt;
        float bj = b1[j];
#pragma unroll
        for (int gg = 0; gg < 4; gg++) {
            float2 p = *(float2*)&acc[gg][jj];
            float a = p.x + p.y + bj;
            float ge = 0.5f * a * (1.0f + erff(a * 0.7071067811865476f));
            hid[(nbase + g0 + gg) * HID + j] = ge;
        }
    }
}

// ---------------- FFN layer 2: out = hid @ w2^T + b2 ------------------------
#define SW2 (HID + 4)    // 260
__global__ void __launch_bounds__(256) ffn2_kernel(
        const float* __restrict__ hidp, const float* __restrict__ w2,
        const float* __restrict__ b2, float* __restrict__ out) {
    extern __shared__ float sm[];
    float* s_w = sm;                 // 128 x SW2
    float* s_h = sm + 128 * SW2;     // 32 x SW2
    int tid = threadIdx.x;
    long nbase = (long)blockIdx.x * 32;

    const float4* wg = (const float4*)w2;
    for (int idx = tid; idx < 128 * 64; idx += 256) {
        int j = idx >> 6, kq = idx & 63;
        *(float4*)&s_w[j * SW2 + kq * 4] = wg[idx];
    }
    const float4* hg = (const float4*)(hidp + nbase * HID);
    for (int idx = tid; idx < 32 * 64; idx += 256) {
        int g = idx >> 6, kq = idx & 63;
        *(float4*)&s_h[g * SW2 + kq * 4] = hg[idx];
    }
    __syncthreads();

    int jt = tid & 31;
    int g0 = (tid >> 5) * 4;

    u64 acc[4][4];
#pragma unroll
    for (int a = 0; a < 4; a++)
#pragma unroll
        for (int b = 0; b < 4; b++) acc[a][b] = 0ull;

    const float* hp = s_h + g0 * SW2;
    const float* wp = s_w + jt * SW2;

#pragma unroll 4
    for (int k = 0; k < HID; k += 4) {
        float4 h4[4], w4[4];
#pragma unroll
        for (int gg = 0; gg < 4; gg++) h4[gg] = *(const float4*)(hp + gg * SW2 + k);
#pragma unroll
        for (int jj = 0; jj < 4; jj++) w4[jj] = *(const float4*)(wp + jj * 32 * SW2 + k);
#pragma unroll
        for (int gg = 0; gg < 4; gg++) {
            u64 h01 = ((const u64*)&h4[gg])[0];
            u64 h23 = ((const u64*)&h4[gg])[1];
#pragma unroll
            for (int jj = 0; jj < 4; jj++) {
                u64 w01 = ((const u64*)&w4[jj])[0];
                u64 w23 = ((const u64*)&w4[jj])[1];
                acc[gg][jj] = ffma2(h01, w01, acc[gg][jj]);
                acc[gg][jj] = ffma2(h23, w23, acc[gg][jj]);
            }
        }
    }

#pragma unroll
    for (int jj = 0; jj < 4; jj++) {
        int j = jj * 32 + jt;
        float bj = b2[j];
#pragma unroll
        for (int gg = 0; gg < 4; gg++) {
            float2 p = *(float2*)&acc[gg][jj];
            out[(nbase + g0 + gg) * DIM + j] = p.x + p.y + bj;
        }
    }
}

// ---------------- launch ----------------------------------------------------
extern "C" void kernel_launch(void* const* d_in, const int* in_sizes, int n_in,
                              void* d_out, int out_size) {
    const float* x   = (const float*)d_in[0];
    const float* rep = (const float*)d_in[1];
    const int*   src = (const int*)d_in[2];
    const int*   dst = (const int*)d_in[3];
    const float* w1  = (const float*)d_in[4];
    const float* b1  = (const float*)d_in[5];
    const float* w2  = (const float*)d_in[6];
    const float* b2  = (const float*)d_in[7];
    float* out = (float*)d_out;

    static int smem_set = 0;
    int smem1 = (128 * SW1 + 32 * SW1) * 4;
    int smem2 = (128 * SW2 + 32 * SW2) * 4;
    if (!smem_set) {
        cudaFuncSetAttribute(ffn1_kernel, cudaFuncAttributeMaxDynamicSharedMemorySize, smem1);
        cudaFuncSetAttribute(ffn2_kernel, cudaFuncAttributeMaxDynamicSharedMemorySize, smem2);
        smem_set = 1;
    }

    float *ha, *hb, *hc, *hidp, *degp, *coefp;
    cudaGetSymbolAddress((void**)&ha,   g_ha);
    cudaGetSymbolAddress((void**)&hb,   g_hb);
    cudaGetSymbolAddress((void**)&hc,   g_hc);
    cudaGetSymbolAddress((void**)&hidp, g_hid);
    cudaGetSymbolAddress((void**)&degp, g_deg);
    cudaGetSymbolAddress((void**)&coefp, g_coef);

    detect_kernel<<<1, 1>>>(src);

    zero_kernel<<<(N_NODES / 4 + 255) / 256, 256>>>(degp, N_NODES / 4);
    deg_kernel<<<N_EDGES / 256, 256>>>(src);
    coef_kernel<<<N_EDGES / 256, 256>>>(src, dst);

    // forward rotation x -> ha, zero hb & hc in the same pass
    rot_kernel<<<(N_NODES * DIM) / 256, 256>>>(x, rep, ha, hb, hc);

    // message passing: ha -> hb -> hc
    scatter_kernel<<<(N_EDGES * 32) / 256, 256>>>(ha, hb, src, dst, coefp);
    scatter_kernel<<<(N_EDGES * 32) / 256, 256>>>(hb, hc, src, dst, coefp);

    // inverse rotation: hc -> ha
    rot_t_kernel<<<(N_NODES * DIM) / 256, 256>>>(hc, rep, ha);

    // FFN
    dim3 g1(N_NODES / 32, 2);
    ffn1_kernel<<<g1, 256, smem1>>>(ha, w1, b1, hidp);
    ffn2_kernel<<<N_NODES / 32, 256, smem2>>>(hidp, w2, b2, out);
}

// round 4
// speedup vs baseline: 2.3218x; 1.1197x over previous
#include <cuda_runtime.h>

#define N_NODES 100000
#define N_EDGES 1600000
#define DIM 128
#define HID 256

typedef unsigned long long u64;

// ---------------- scratch (static device globals; no allocs allowed) --------
__device__ float g_deg[N_NODES];
__device__ int   g_cnt[N_NODES];        // in-degree histogram
__device__ int   g_row[N_NODES + 1];    // CSR row offsets (by dst)
__device__ int   g_fill[N_NODES];       // fill cursors
__device__ int2  g_csr[N_EDGES];        // (src, coef-as-int) grouped by dst
__device__ float g_ha[N_NODES * DIM];
__device__ float g_hb[N_NODES * DIM];
__device__ float g_hid[N_NODES * HID];
__device__ int   g_sh;                  // 0: int32 indices, 1: int64

// packed f32x2 FMA (Blackwell)
__device__ __forceinline__ u64 ffma2(u64 a, u64 b, u64 c) {
    u64 d;
    asm("fma.rn.f32x2 %0, %1, %2, %3;" : "=l"(d) : "l"(a), "l"(b), "l"(c));
    return d;
}

// ---------------- small utility kernels ------------------------------------
__global__ void detect_kernel(const int* __restrict__ src) {
    if (blockIdx.x == 0 && threadIdx.x == 0)
        g_sh = (src[1] == 0 && src[2] == 1) ? 1 : 0;
}

__global__ void zero_deg_cnt_kernel() {
    int i = blockIdx.x * blockDim.x + threadIdx.x;
    if (i < N_NODES) { g_deg[i] = 0.f; g_cnt[i] = 0; }
}

// out-degree (float, on src) + in-degree histogram (int, on dst)
__global__ void deg_hist_kernel(const int* __restrict__ src, const int* __restrict__ dst) {
    int e = blockIdx.x * blockDim.x + threadIdx.x;
    if (e < N_EDGES) {
        int sh = g_sh;
        atomicAdd(&g_deg[src[(long)e << sh]], 1.0f);
        atomicAdd(&g_cnt[dst[(long)e << sh]], 1);
    }
}

// single-block exclusive scan of g_cnt -> g_row / g_fill
__global__ void scan_kernel() {
    __shared__ int s[1024];
    const int CH = (N_NODES + 1023) / 1024;   // 98
    int t = threadIdx.x;
    int beg = t * CH;
    int end = beg + CH; if (end > N_NODES) end = N_NODES;
    if (beg > N_NODES) beg = N_NODES;
    int sum = 0;
    for (int i = beg; i < end; i++) sum += g_cnt[i];
    s[t] = sum;
    __syncthreads();
    for (int off = 1; off < 1024; off <<= 1) {
        int v = 0;
        if (t >= off) v = s[t - off];
        __syncthreads();
        if (t >= off) s[t] += v;
        __syncthreads();
    }
    int run = (t > 0) ? s[t - 1] : 0;
    for (int i = beg; i < end; i++) {
        g_row[i] = run;
        g_fill[i] = run;
        run += g_cnt[i];
    }
    if (t == 0) g_row[N_NODES] = s[1023];
}

// fill CSR: coef computed inline
__global__ void fill_kernel(const int* __restrict__ src, const int* __restrict__ dst) {
    int e = blockIdx.x * blockDim.x + threadIdx.x;
    if (e < N_EDGES) {
        int sh = g_sh;
        int s = src[(long)e << sh];
        int d = dst[(long)e << sh];
        float c = rsqrtf(g_deg[s] * g_deg[d]);
        int pos = atomicAdd(&g_fill[d], 1);
        g_csr[pos] = make_int2(s, __float_as_int(c));
    }
}

// ---------------- bundle rotations ------------------------------------------
__global__ void rot_kernel(const float* __restrict__ x, const float* __restrict__ rep,
                           float* __restrict__ out) {
    int i = blockIdx.x * blockDim.x + threadIdx.x;
    int n = i >> 7;
    int t = i & 127;
    int b = t >> 4, c = (t >> 2) & 3, el = t & 3;
    float4 r = *(const float4*)(rep + (((long)n * 8 + b) * 16 + c * 4));
    const float* xb = x + (long)n * DIM + b * 16 + el;
    out[i] = r.x * xb[0] + r.y * xb[4] + r.z * xb[8] + r.w * xb[12];
}

__global__ void rot_t_kernel(const float* __restrict__ h, const float* __restrict__ rep,
                             float* __restrict__ out) {
    int i = blockIdx.x * blockDim.x + threadIdx.x;
    int n = i >> 7;
    int t = i & 127;
    int b = t >> 4, c = (t >> 2) & 3, el = t & 3;
    const float* rb = rep + (((long)n * 8 + b) * 16 + c);
    const float* hb = h + (long)n * DIM + b * 16 + el;
    out[i] = rb[0] * hb[0] + rb[4] * hb[4] + rb[8] * hb[8] + rb[12] * hb[12];
}

// ---------------- gather: hout[d] = sum_{e in in(d)} hin[src[e]] * coef[e] ---
// One warp per dst node; lane owns one float4 of the 128-dim row.
__global__ void gather_kernel(const float* __restrict__ hin, float* __restrict__ hout) {
    int gid = blockIdx.x * blockDim.x + threadIdx.x;
    int n = gid >> 5;
    int lane = gid & 31;
    int beg = g_row[n], end = g_row[n + 1];
    float4 acc = make_float4(0.f, 0.f, 0.f, 0.f);
    int e = beg;
    for (; e + 2 <= end; e += 2) {
        int2 c0 = g_csr[e];
        int2 c1 = g_csr[e + 1];
        float4 v0 = __ldg((const float4*)(hin + (long)c0.x * DIM + lane * 4));
        float4 v1 = __ldg((const float4*)(hin + (long)c1.x * DIM + lane * 4));
        float f0 = __int_as_float(c0.y), f1 = __int_as_float(c1.y);
        acc.x += v0.x * f0; acc.y += v0.y * f0; acc.z += v0.z * f0; acc.w += v0.w * f0;
        acc.x += v1.x * f1; acc.y += v1.y * f1; acc.z += v1.z * f1; acc.w += v1.w * f1;
    }
    if (e < end) {
        int2 c0 = g_csr[e];
        float4 v0 = __ldg((const float4*)(hin + (long)c0.x * DIM + lane * 4));
        float f0 = __int_as_float(c0.y);
        acc.x += v0.x * f0; acc.y += v0.y * f0; acc.z += v0.z * f0; acc.w += v0.w * f0;
    }
    *(float4*)(hout + (long)n * DIM + lane * 4) = acc;
}

// ---------------- FFN layer 1: hid = gelu(h @ w1^T + b1) --------------------
// Block: 256 thr, tile 64 nodes x 128 hidden (blockIdx.y = hidden half).
// Thread tile 8g x 4j, j strided by 32.
#define SW1 (DIM + 4)    // 132
__global__ void __launch_bounds__(256) ffn1_kernel(
        const float* __restrict__ hin, const float* __restrict__ w1,
        const float* __restrict__ b1, float* __restrict__ hid) {
    extern __shared__ float sm[];
    float* s_w = sm;                 // 128 x SW1
    float* s_h = sm + 128 * SW1;     // 64 x SW1
    int tid = threadIdx.x;
    int jhalf = blockIdx.y;
    long nbase = (long)blockIdx.x * 64;

    const float4* wg = (const float4*)(w1 + (long)jhalf * 128 * DIM);
    for (int idx = tid; idx < 128 * 32; idx += 256) {
        int j = idx >> 5, kq = idx & 31;
        *(float4*)&s_w[j * SW1 + kq * 4] = wg[idx];
    }
    for (int idx = tid; idx < 64 * 32; idx += 256) {
        int g = idx >> 5, kq = idx & 31;
        long n = nbase + g; if (n >= N_NODES) n = N_NODES - 1;
        *(float4*)&s_h[g * SW1 + kq * 4] = *(const float4*)(hin + n * DIM + kq * 4);
    }
    __syncthreads();

    int jt = tid & 31;
    int g0 = (tid >> 5) * 8;

    u64 acc[8][4];
#pragma unroll
    for (int a = 0; a < 8; a++)
#pragma unroll
        for (int b = 0; b < 4; b++) acc[a][b] = 0ull;

    const float* hp = s_h + g0 * SW1;
    const float* wp = s_w + jt * SW1;

#pragma unroll 2
    for (int k = 0; k < DIM; k += 4) {
        float4 w4[4];
#pragma unroll
        for (int jj = 0; jj < 4; jj++) w4[jj] = *(const float4*)(wp + jj * 32 * SW1 + k);
#pragma unroll
        for (int gg = 0; gg < 8; gg++) {
            float4 h4 = *(const float4*)(hp + gg * SW1 + k);
            u64 h01 = ((const u64*)&h4)[0];
            u64 h23 = ((const u64*)&h4)[1];
#pragma unroll
            for (int jj = 0; jj < 4; jj++) {
                acc[gg][jj] = ffma2(h01, ((const u64*)&w4[jj])[0], acc[gg][jj]);
                acc[gg][jj] = ffma2(h23, ((const u64*)&w4[jj])[1], acc[gg][jj]);
            }
        }
    }

#pragma unroll
    for (int jj = 0; jj < 4; jj++) {
        int j = jhalf * 128 + jj * 32 + jt;
        float bj = b1[j];
#pragma unroll
        for (int gg = 0; gg < 8; gg++) {
            long n = nbase + g0 + gg;
            if (n < N_NODES) {
                float2 p = *(float2*)&acc[gg][jj];
                float a = p.x + p.y + bj;
                hid[n * HID + j] = 0.5f * a * (1.0f + erff(a * 0.7071067811865476f));
            }
        }
    }
}

// ---------------- FFN layer 2: out = hid @ w2^T + b2 ------------------------
#define SW2 (HID + 4)    // 260
__global__ void __launch_bounds__(256) ffn2_kernel(
        const float* __restrict__ hidp, const float* __restrict__ w2,
        const float* __restrict__ b2, float* __restrict__ out) {
    extern __shared__ float sm[];
    float* s_w = sm;                 // 128 x SW2
    float* s_h = sm + 128 * SW2;     // 64 x SW2
    int tid = threadIdx.x;
    long nbase = (long)blockIdx.x * 64;

    const float4* wg = (const float4*)w2;
    for (int idx = tid; idx < 128 * 64; idx += 256) {
        int j = idx >> 6, kq = idx & 63;
        *(float4*)&s_w[j * SW2 + kq * 4] = wg[idx];
    }
    for (int idx = tid; idx < 64 * 64; idx += 256) {
        int g = idx >> 6, kq = idx & 63;
        long n = nbase + g; if (n >= N_NODES) n = N_NODES - 1;
        *(float4*)&s_h[g * SW2 + kq * 4] = *(const float4*)(hidp + n * HID + kq * 4);
    }
    __syncthreads();

    int jt = tid & 31;
    int g0 = (tid >> 5) * 8;

    u64 acc[8][4];
#pragma unroll
    for (int a = 0; a < 8; a++)
#pragma unroll
        for (int b = 0; b < 4; b++) acc[a][b] = 0ull;

    const float* hp = s_h + g0 * SW2;
    const float* wp = s_w + jt * SW2;

#pragma unroll 2
    for (int k = 0; k < HID; k += 4) {
        float4 w4[4];
#pragma unroll
        for (int jj = 0; jj < 4; jj++) w4[jj] = *(const float4*)(wp + jj * 32 * SW2 + k);
#pragma unroll
        for (int gg = 0; gg < 8; gg++) {
            float4 h4 = *(const float4*)(hp + gg * SW2 + k);
            u64 h01 = ((const u64*)&h4)[0];
            u64 h23 = ((const u64*)&h4)[1];
#pragma unroll
            for (int jj = 0; jj < 4; jj++) {
                acc[gg][jj] = ffma2(h01, ((const u64*)&w4[jj])[0], acc[gg][jj]);
                acc[gg][jj] = ffma2(h23, ((const u64*)&w4[jj])[1], acc[gg][jj]);
            }
        }
    }

#pragma unroll
    for (int jj = 0; jj < 4; jj++) {
        int j = jj * 32 + jt;
        float bj = b2[j];
#pragma unroll
        for (int gg = 0; gg < 8; gg++) {
            long n = nbase + g0 + gg;
            if (n < N_NODES) {
                float2 p = *(float2*)&acc[gg][jj];
                out[n * DIM + j] = p.x + p.y + bj;
            }
        }
    }
}

// ---------------- launch ----------------------------------------------------
extern "C" void kernel_launch(void* const* d_in, const int* in_sizes, int n_in,
                              void* d_out, int out_size) {
    const float* x   = (const float*)d_in[0];
    const float* rep = (const float*)d_in[1];
    const int*   src = (const int*)d_in[2];
    const int*   dst = (const int*)d_in[3];
    const float* w1  = (const float*)d_in[4];
    const float* b1  = (const float*)d_in[5];
    const float* w2  = (const float*)d_in[6];
    const float* b2  = (const float*)d_in[7];
    float* out = (float*)d_out;

    static int smem_set = 0;
    int smem1 = (128 * SW1 + 64 * SW1) * 4;   // 101,376 B
    int smem2 = (128 * SW2 + 64 * SW2) * 4;   // 199,680 B
    if (!smem_set) {
        cudaFuncSetAttribute(ffn1_kernel, cudaFuncAttributeMaxDynamicSharedMemorySize, smem1);
        cudaFuncSetAttribute(ffn2_kernel, cudaFuncAttributeMaxDynamicSharedMemorySize, smem2);
        smem_set = 1;
    }

    float *ha, *hb, *hidp;
    cudaGetSymbolAddress((void**)&ha,   g_ha);
    cudaGetSymbolAddress((void**)&hb,   g_hb);
    cudaGetSymbolAddress((void**)&hidp, g_hid);

    detect_kernel<<<1, 1>>>(src);

    // CSR build (per call; graph is an input)
    zero_deg_cnt_kernel<<<(N_NODES + 255) / 256, 256>>>();
    deg_hist_kernel<<<N_EDGES / 256, 256>>>(src, dst);
    scan_kernel<<<1, 1024>>>();
    fill_kernel<<<N_EDGES / 256, 256>>>(src, dst);

    // forward rotation x -> ha
    rot_kernel<<<(N_NODES * DIM) / 256, 256>>>(x, rep, ha);

    // message passing: ha -> hb -> ha (gather, no atomics)
    gather_kernel<<<(N_NODES * 32 + 255) / 256, 256>>>(ha, hb);
    gather_kernel<<<(N_NODES * 32 + 255) / 256, 256>>>(hb, ha);

    // inverse rotation: ha -> hb
    rot_t_kernel<<<(N_NODES * DIM) / 256, 256>>>(ha, rep, hb);

    // FFN
    dim3 g1((N_NODES + 63) / 64, 2);
    ffn1_kernel<<<g1, 256, smem1>>>(hb, w1, b1, hidp);
    ffn2_kernel<<<(N_NODES + 63) / 64, 256, smem2>>>(hidp, w2, b2, out);
}

// round 5
// speedup vs baseline: 3.0534x; 1.3151x over previous
#include <cuda_runtime.h>

#define N_NODES 100000
#define N_EDGES 1600000
#define DIM 128
#define HID 256
#define SCAN_B 98            // ceil(100000/1024)

typedef unsigned long long u64;

// ---------------- scratch (static device globals; no allocs allowed) --------
__device__ float g_deg[N_NODES];
__device__ int   g_cnt[N_NODES];        // in-degree histogram
__device__ int   g_part[SCAN_B];        // per-block partial sums
__device__ int   g_row[N_NODES + 1];    // CSR row offsets (by dst)
__device__ int   g_fill[N_NODES];       // fill cursors
__device__ int2  g_csr[N_EDGES];        // (src, coef-as-int) grouped by dst
__device__ float g_ha[N_NODES * DIM];
__device__ float g_hb[N_NODES * DIM];
__device__ float g_hid[N_NODES * HID];
__device__ int   g_sh;                  // 0: int32 indices, 1: int64

// packed f32x2 FMA (Blackwell)
__device__ __forceinline__ u64 ffma2(u64 a, u64 b, u64 c) {
    u64 d;
    asm("fma.rn.f32x2 %0, %1, %2, %3;" : "=l"(d) : "l"(a), "l"(b), "l"(c));
    return d;
}

// ---------------- init: zero deg/cnt + index-width detect --------------------
__global__ void init_kernel(const int* __restrict__ src) {
    int i = blockIdx.x * blockDim.x + threadIdx.x;
    if (i < N_NODES) { g_deg[i] = 0.f; g_cnt[i] = 0; }
    if (i == 0) g_sh = (src[1] == 0 && src[2] == 1) ? 1 : 0;
}

// out-degree (float, on src) + in-degree histogram (int, on dst)
__global__ void deg_hist_kernel(const int* __restrict__ src, const int* __restrict__ dst) {
    int e = blockIdx.x * blockDim.x + threadIdx.x;
    if (e < N_EDGES) {
        int sh = g_sh;
        atomicAdd(&g_deg[src[(long)e << sh]], 1.0f);
        atomicAdd(&g_cnt[dst[(long)e << sh]], 1);
    }
}

// ---------------- hierarchical scan of g_cnt -> g_row / g_fill ---------------
// Phase A: per-block sum of 1024 counts.
__global__ void scan_a_kernel() {
    __shared__ int s[1024];
    int t = threadIdx.x;
    int i = blockIdx.x * 1024 + t;
    s[t] = (i < N_NODES) ? g_cnt[i] : 0;
    __syncthreads();
    for (int off = 512; off > 0; off >>= 1) {
        if (t < off) s[t] += s[t + off];
        __syncthreads();
    }
    if (t == 0) g_part[blockIdx.x] = s[0];
}

// Phase B+C: each block scans the 98 partials (redundantly) for its base,
// then does a local inclusive scan of its 1024 counts and writes offsets.
__global__ void scan_c_kernel() {
    __shared__ int s[1024];
    __shared__ int base_s;
    int t = threadIdx.x;
    int b = blockIdx.x;
    int i = b * 1024 + t;
    int v = (i < N_NODES) ? g_cnt[i] : 0;
    s[t] = v;
    if (t == 0) {
        int base = 0;
        for (int k = 0; k < b; k++) base += g_part[k];
        base_s = base;
    }
    __syncthreads();
    // Hillis-Steele inclusive scan
    for (int off = 1; off < 1024; off <<= 1) {
        int add = (t >= off) ? s[t - off] : 0;
        __syncthreads();
        s[t] += add;
        __syncthreads();
    }
    int base = base_s;
    if (i < N_NODES) {
        int excl = base + s[t] - v;
        g_row[i] = excl;
        g_fill[i] = excl;
        if (i == N_NODES - 1) g_row[N_NODES] = base + s[t];
    }
}

// fill CSR: coef computed inline
__global__ void fill_kernel(const int* __restrict__ src, const int* __restrict__ dst) {
    int e = blockIdx.x * blockDim.x + threadIdx.x;
    if (e < N_EDGES) {
        int sh = g_sh;
        int s = src[(long)e << sh];
        int d = dst[(long)e << sh];
        float c = rsqrtf(g_deg[s] * g_deg[d]);
        int pos = atomicAdd(&g_fill[d], 1);
        g_csr[pos] = make_int2(s, __float_as_int(c));
    }
}

// ---------------- bundle rotations ------------------------------------------
__global__ void rot_kernel(const float* __restrict__ x, const float* __restrict__ rep,
                           float* __restrict__ out) {
    int i = blockIdx.x * blockDim.x + threadIdx.x;
    int n = i >> 7;
    int t = i & 127;
    int b = t >> 4, c = (t >> 2) & 3, el = t & 3;
    float4 r = *(const float4*)(rep + (((long)n * 8 + b) * 16 + c * 4));
    const float* xb = x + (long)n * DIM + b * 16 + el;
    out[i] = r.x * xb[0] + r.y * xb[4] + r.z * xb[8] + r.w * xb[12];
}

__global__ void rot_t_kernel(const float* __restrict__ h, const float* __restrict__ rep,
                             float* __restrict__ out) {
    int i = blockIdx.x * blockDim.x + threadIdx.x;
    int n = i >> 7;
    int t = i & 127;
    int b = t >> 4, c = (t >> 2) & 3, el = t & 3;
    const float* rb = rep + (((long)n * 8 + b) * 16 + c);
    const float* hb = h + (long)n * DIM + b * 16 + el;
    out[i] = rb[0] * hb[0] + rb[4] * hb[4] + rb[8] * hb[8] + rb[12] * hb[12];
}

// ---------------- gather: hout[d] = sum_{e in in(d)} hin[src[e]] * coef[e] ---
__global__ void gather_kernel(const float* __restrict__ hin, float* __restrict__ hout) {
    int gid = blockIdx.x * blockDim.x + threadIdx.x;
    int n = gid >> 5;
    int lane = gid & 31;
    int beg = g_row[n], end = g_row[n + 1];
    float4 acc = make_float4(0.f, 0.f, 0.f, 0.f);
    int e = beg;
    for (; e + 2 <= end; e += 2) {
        int2 c0 = g_csr[e];
        int2 c1 = g_csr[e + 1];
        float4 v0 = __ldg((const float4*)(hin + (long)c0.x * DIM + lane * 4));
        float4 v1 = __ldg((const float4*)(hin + (long)c1.x * DIM + lane * 4));
        float f0 = __int_as_float(c0.y), f1 = __int_as_float(c1.y);
        acc.x += v0.x * f0; acc.y += v0.y * f0; acc.z += v0.z * f0; acc.w += v0.w * f0;
        acc.x += v1.x * f1; acc.y += v1.y * f1; acc.z += v1.z * f1; acc.w += v1.w * f1;
    }
    if (e < end) {
        int2 c0 = g_csr[e];
        float4 v0 = __ldg((const float4*)(hin + (long)c0.x * DIM + lane * 4));
        float f0 = __int_as_float(c0.y);
        acc.x += v0.x * f0; acc.y += v0.y * f0; acc.z += v0.z * f0; acc.w += v0.w * f0;
    }
    *(float4*)(hout + (long)n * DIM + lane * 4) = acc;
}

// ---------------- FFN layer 1: hid = gelu(h @ w1^T + b1) --------------------
// Block: 512 thr (16 warps), tile 64 nodes x 128 hidden (blockIdx.y = half).
// Thread tile 4g x 4j; j strided by 32 across jt lanes; h loads are warp
// broadcasts (whole warp shares g0).
#define SW1 (DIM + 4)    // 132
__global__ void __launch_bounds__(512) ffn1_kernel(
        const float* __restrict__ hin, const float* __restrict__ w1,
        const float* __restrict__ b1, float* __restrict__ hid) {
    extern __shared__ float sm[];
    float* s_w = sm;                 // 128 x SW1
    float* s_h = sm + 128 * SW1;     // 64 x SW1
    int tid = threadIdx.x;
    int jhalf = blockIdx.y;
    long nbase = (long)blockIdx.x * 64;

    const float4* wg = (const float4*)(w1 + (long)jhalf * 128 * DIM);
    for (int idx = tid; idx < 128 * 32; idx += 512) {
        int j = idx >> 5, kq = idx & 31;
        *(float4*)&s_w[j * SW1 + kq * 4] = wg[idx];
    }
    for (int idx = tid; idx < 64 * 32; idx += 512) {
        int g = idx >> 5, kq = idx & 31;
        long n = nbase + g; if (n >= N_NODES) n = N_NODES - 1;
        *(float4*)&s_h[g * SW1 + kq * 4] = *(const float4*)(hin + n * DIM + kq * 4);
    }
    __syncthreads();

    int jt = tid & 31;
    int g0 = (tid >> 5) * 4;

    u64 acc[4][4];
#pragma unroll
    for (int a = 0; a < 4; a++)
#pragma unroll
        for (int b = 0; b < 4; b++) acc[a][b] = 0ull;

    const float* hp = s_h + g0 * SW1;
    const float* wp = s_w + jt * SW1;

#pragma unroll 4
    for (int k = 0; k < DIM; k += 4) {
        float4 w4[4], h4[4];
#pragma unroll
        for (int jj = 0; jj < 4; jj++) w4[jj] = *(const float4*)(wp + jj * 32 * SW1 + k);
#pragma unroll
        for (int gg = 0; gg < 4; gg++) h4[gg] = *(const float4*)(hp + gg * SW1 + k);
#pragma unroll
        for (int gg = 0; gg < 4; gg++) {
            u64 h01 = ((const u64*)&h4[gg])[0];
            u64 h23 = ((const u64*)&h4[gg])[1];
#pragma unroll
            for (int jj = 0; jj < 4; jj++) {
                acc[gg][jj] = ffma2(h01, ((const u64*)&w4[jj])[0], acc[gg][jj]);
                acc[gg][jj] = ffma2(h23, ((const u64*)&w4[jj])[1], acc[gg][jj]);
            }
        }
    }

#pragma unroll
    for (int jj = 0; jj < 4; jj++) {
        int j = jhalf * 128 + jj * 32 + jt;
        float bj = b1[j];
#pragma unroll
        for (int gg = 0; gg < 4; gg++) {
            long n = nbase + g0 + gg;
            if (n < N_NODES) {
                float2 p = *(float2*)&acc[gg][jj];
                float a = p.x + p.y + bj;
                hid[n * HID + j] = 0.5f * a * (1.0f + erff(a * 0.7071067811865476f));
            }
        }
    }
}

// ---------------- FFN layer 2: out = hid @ w2^T + b2 ------------------------
#define SW2 (HID + 4)    // 260
__global__ void __launch_bounds__(512) ffn2_kernel(
        const float* __restrict__ hidp, const float* __restrict__ w2,
        const float* __restrict__ b2, float* __restrict__ out) {
    extern __shared__ float sm[];
    float* s_w = sm;                 // 128 x SW2
    float* s_h = sm + 128 * SW2;     // 64 x SW2
    int tid = threadIdx.x;
    long nbase = (long)blockIdx.x * 64;

    const float4* wg = (const float4*)w2;
    for (int idx = tid; idx < 128 * 64; idx += 512) {
        int j = idx >> 6, kq = idx & 63;
        *(float4*)&s_w[j * SW2 + kq * 4] = wg[idx];
    }
    for (int idx = tid; idx < 64 * 64; idx += 512) {
        int g = idx >> 6, kq = idx & 63;
        long n = nbase + g; if (n >= N_NODES) n = N_NODES - 1;
        *(float4*)&s_h[g * SW2 + kq * 4] = *(const float4*)(hidp + n * HID + kq * 4);
    }
    __syncthreads();

    int jt = tid & 31;
    int g0 = (tid >> 5) * 4;

    u64 acc[4][4];
#pragma unroll
    for (int a = 0; a < 4; a++)
#pragma unroll
        for (int b = 0; b < 4; b++) acc[a][b] = 0ull;

    const float* hp = s_h + g0 * SW2;
    const float* wp = s_w + jt * SW2;

#pragma unroll 4
    for (int k = 0; k < HID; k += 4) {
        float4 w4[4], h4[4];
#pragma unroll
        for (int jj = 0; jj < 4; jj++) w4[jj] = *(const float4*)(wp + jj * 32 * SW2 + k);
#pragma unroll
        for (int gg = 0; gg < 4; gg++) h4[gg] = *(const float4*)(hp + gg * SW2 + k);
#pragma unroll
        for (int gg = 0; gg < 4; gg++) {
            u64 h01 = ((const u64*)&h4[gg])[0];
            u64 h23 = ((const u64*)&h4[gg])[1];
#pragma unroll
            for (int jj = 0; jj < 4; jj++) {
                acc[gg][jj] = ffma2(h01, ((const u64*)&w4[jj])[0], acc[gg][jj]);
                acc[gg][jj] = ffma2(h23, ((const u64*)&w4[jj])[1], acc[gg][jj]);
            }
        }
    }

#pragma unroll
    for (int jj = 0; jj < 4; jj++) {
        int j = jj * 32 + jt;
        float bj = b2[j];
#pragma unroll
        for (int gg = 0; gg < 4; gg++) {
            long n = nbase + g0 + gg;
            if (n < N_NODES) {
                float2 p = *(float2*)&acc[gg][jj];
                out[n * DIM + j] = p.x + p.y + bj;
            }
        }
    }
}

// ---------------- launch ----------------------------------------------------
extern "C" void kernel_launch(void* const* d_in, const int* in_sizes, int n_in,
                              void* d_out, int out_size) {
    const float* x   = (const float*)d_in[0];
    const float* rep = (const float*)d_in[1];
    const int*   src = (const int*)d_in[2];
    const int*   dst = (const int*)d_in[3];
    const float* w1  = (const float*)d_in[4];
    const float* b1  = (const float*)d_in[5];
    const float* w2  = (const float*)d_in[6];
    const float* b2  = (const float*)d_in[7];
    float* out = (float*)d_out;

    static int smem_set = 0;
    int smem1 = (128 * SW1 + 64 * SW1) * 4;   // 101,376 B
    int smem2 = (128 * SW2 + 64 * SW2) * 4;   // 199,680 B
    if (!smem_set) {
        cudaFuncSetAttribute(ffn1_kernel, cudaFuncAttributeMaxDynamicSharedMemorySize, smem1);
        cudaFuncSetAttribute(ffn2_kernel, cudaFuncAttributeMaxDynamicSharedMemorySize, smem2);
        smem_set = 1;
    }

    float *ha, *hb, *hidp;
    cudaGetSymbolAddress((void**)&ha,   g_ha);
    cudaGetSymbolAddress((void**)&hb,   g_hb);
    cudaGetSymbolAddress((void**)&hidp, g_hid);

    // CSR build
    init_kernel<<<(N_NODES + 255) / 256, 256>>>(src);
    deg_hist_kernel<<<N_EDGES / 256, 256>>>(src, dst);
    scan_a_kernel<<<SCAN_B, 1024>>>();
    scan_c_kernel<<<SCAN_B, 1024>>>();
    fill_kernel<<<N_EDGES / 256, 256>>>(src, dst);

    // forward rotation x -> ha
    rot_kernel<<<(N_NODES * DIM) / 256, 256>>>(x, rep, ha);

    // message passing: ha -> hb -> ha (gather, no atomics)
    gather_kernel<<<(N_NODES * 32) / 256, 256>>>(ha, hb);
    gather_kernel<<<(N_NODES * 32) / 256, 256>>>(hb, ha);

    // inverse rotation: ha -> hb
    rot_t_kernel<<<(N_NODES * DIM) / 256, 256>>>(ha, rep, hb);

    // FFN
    dim3 g1((N_NODES + 63) / 64, 2);
    ffn1_kernel<<<g1, 512, smem1>>>(hb, w1, b1, hidp);
    ffn2_kernel<<<(N_NODES + 63) / 64, 512, smem2>>>(hidp, w2, b2, out);
}

// round 8
// speedup vs baseline: 3.4468x; 1.1289x over previous
#include <cuda_runtime.h>
#include <cuda_bf16.h>

#define N_NODES 100000
#define N_EDGES 1600000
#define DIM 128
#define HID 256
#define SCAN_B 98

typedef unsigned long long u64;
typedef unsigned int u32;

// ---------------- scratch (static device globals; no allocs allowed) --------
__device__ float g_deg[N_NODES];
__device__ int   g_cnt[N_NODES];
__device__ int   g_part[SCAN_B];
__device__ int   g_row[N_NODES + 1];
__device__ int   g_fill[N_NODES];
__device__ int2  g_csr[N_EDGES];
__device__ float g_ha[N_NODES * DIM];
__device__ float g_hb[N_NODES * DIM];
__device__ __nv_bfloat16 g_hhi[N_NODES * DIM];
__device__ __nv_bfloat16 g_hlo[N_NODES * DIM];
__device__ __nv_bfloat16 g_hidhi[(long)N_NODES * HID];
__device__ __nv_bfloat16 g_hidlo[(long)N_NODES * HID];
__device__ __nv_bfloat16 g_w1h[HID * DIM], g_w1l[HID * DIM];
__device__ __nv_bfloat16 g_w2h[DIM * HID], g_w2l[DIM * HID];
__device__ int   g_sh;

// ---------------- warp-MMA helpers (sm_80+ PTX, valid on plain sm_103) ------
__device__ __forceinline__ u32 smem_u32(const void* p) {
    u32 a;
    asm("{ .reg .u64 t; cvta.to.shared.u64 t, %1; cvt.u32.u64 %0, t; }" : "=r"(a) : "l"(p));
    return a;
}
__device__ __forceinline__ void ldsm4(u32* r, u32 a) {
    asm volatile("ldmatrix.sync.aligned.m8n8.x4.shared.b16 {%0,%1,%2,%3}, [%4];"
                 : "=r"(r[0]), "=r"(r[1]), "=r"(r[2]), "=r"(r[3]) : "r"(a));
}
// non-transposed x2: correct B fragment from [n][k] row-major storage
__device__ __forceinline__ void ldsm2(u32* r, u32 a) {
    asm volatile("ldmatrix.sync.aligned.m8n8.x2.shared.b16 {%0,%1}, [%2];"
                 : "=r"(r[0]), "=r"(r[1]) : "r"(a));
}
__device__ __forceinline__ void mma16816(float* c, const u32* a, const u32* b) {
    asm volatile("mma.sync.aligned.m16n8k16.row.col.f32.bf16.bf16.f32 "
                 "{%0,%1,%2,%3}, {%4,%5,%6,%7}, {%8,%9}, {%0,%1,%2,%3};"
                 : "+f"(c[0]), "+f"(c[1]), "+f"(c[2]), "+f"(c[3])
                 : "r"(a[0]), "r"(a[1]), "r"(a[2]), "r"(a[3]), "r"(b[0]), "r"(b[1]));
}

// ---------------- init / CSR build ------------------------------------------
__global__ void init_kernel(const int* __restrict__ src) {
    int i = blockIdx.x * blockDim.x + threadIdx.x;
    if (i < N_NODES) { g_deg[i] = 0.f; g_cnt[i] = 0; }
    if (i == 0) g_sh = (src[1] == 0 && src[2] == 1) ? 1 : 0;
}

__global__ void deg_hist_kernel(const int* __restrict__ src, const int* __restrict__ dst) {
    int e = blockIdx.x * blockDim.x + threadIdx.x;
    if (e < N_EDGES) {
        int sh = g_sh;
        atomicAdd(&g_deg[src[(long)e << sh]], 1.0f);
        atomicAdd(&g_cnt[dst[(long)e << sh]], 1);
    }
}

__global__ void scan_a_kernel() {
    __shared__ int s[1024];
    int t = threadIdx.x;
    int i = blockIdx.x * 1024 + t;
    s[t] = (i < N_NODES) ? g_cnt[i] : 0;
    __syncthreads();
    for (int off = 512; off > 0; off >>= 1) {
        if (t < off) s[t] += s[t + off];
        __syncthreads();
    }
    if (t == 0) g_part[blockIdx.x] = s[0];
}

__global__ void scan_c_kernel() {
    __shared__ int s[1024];
    __shared__ int base_s;
    int t = threadIdx.x;
    int b = blockIdx.x;
    int i = b * 1024 + t;
    int v = (i < N_NODES) ? g_cnt[i] : 0;
    s[t] = v;
    if (t == 0) {
        int base = 0;
        for (int k = 0; k < b; k++) base += g_part[k];
        base_s = base;
    }
    __syncthreads();
    for (int off = 1; off < 1024; off <<= 1) {
        int add = (t >= off) ? s[t - off] : 0;
        __syncthreads();
        s[t] += add;
        __syncthreads();
    }
    int base = base_s;
    if (i < N_NODES) {
        int excl = base + s[t] - v;
        g_row[i] = excl;
        g_fill[i] = excl;
        if (i == N_NODES - 1) g_row[N_NODES] = base + s[t];
    }
}

__global__ void fill_kernel(const int* __restrict__ src, const int* __restrict__ dst) {
    int e = blockIdx.x * blockDim.x + threadIdx.x;
    if (e < N_EDGES) {
        int sh = g_sh;
        int s = src[(long)e << sh];
        int d = dst[(long)e << sh];
        float c = rsqrtf(g_deg[s] * g_deg[d]);
        int pos = atomicAdd(&g_fill[d], 1);
        g_csr[pos] = make_int2(s, __float_as_int(c));
    }
}

// ---------------- rotations ---------------------------------------------------
__global__ void rot_kernel(const float* __restrict__ x, const float* __restrict__ rep,
                           float* __restrict__ out) {
    int i = blockIdx.x * blockDim.x + threadIdx.x;
    int n = i >> 7;
    int t = i & 127;
    int b = t >> 4, c = (t >> 2) & 3, el = t & 3;
    float4 r = *(const float4*)(rep + (((long)n * 8 + b) * 16 + c * 4));
    const float* xb = x + (long)n * DIM + b * 16 + el;
    out[i] = r.x * xb[0] + r.y * xb[4] + r.z * xb[8] + r.w * xb[12];
}

__global__ void rot_t_split_kernel(const float* __restrict__ h, const float* __restrict__ rep,
                                   __nv_bfloat16* __restrict__ ohi,
                                   __nv_bfloat16* __restrict__ olo) {
    int i = blockIdx.x * blockDim.x + threadIdx.x;
    int n = i >> 7;
    int t = i & 127;
    int b = t >> 4, c = (t >> 2) & 3, el = t & 3;
    const float* rb = rep + (((long)n * 8 + b) * 16 + c);
    const float* hb = h + (long)n * DIM + b * 16 + el;
    float v = rb[0] * hb[0] + rb[4] * hb[4] + rb[8] * hb[8] + rb[12] * hb[12];
    __nv_bfloat16 hi = __float2bfloat16(v);
    ohi[i] = hi;
    olo[i] = __float2bfloat16(v - __bfloat162float(hi));
}

__global__ void wsplit_kernel(const float* __restrict__ w1, const float* __restrict__ w2) {
    int i = blockIdx.x * blockDim.x + threadIdx.x;
    if (i < HID * DIM) {
        float v = w1[i];
        __nv_bfloat16 hi = __float2bfloat16(v);
        g_w1h[i] = hi;
        g_w1l[i] = __float2bfloat16(v - __bfloat162float(hi));
    } else if (i < 2 * HID * DIM) {
        int j = i - HID * DIM;
        float v = w2[j];
        __nv_bfloat16 hi = __float2bfloat16(v);
        g_w2h[j] = hi;
        g_w2l[j] = __float2bfloat16(v - __bfloat162float(hi));
    }
}

// ---------------- gather ------------------------------------------------------
__global__ void gather_kernel(const float* __restrict__ hin, float* __restrict__ hout) {
    int gid = blockIdx.x * blockDim.x + threadIdx.x;
    int n = gid >> 5;
    int lane = gid & 31;
    int beg = g_row[n], end = g_row[n + 1];
    float4 acc = make_float4(0.f, 0.f, 0.f, 0.f);
    int e = beg;
    for (; e + 2 <= end; e += 2) {
        int2 c0 = g_csr[e];
        int2 c1 = g_csr[e + 1];
        float4 v0 = __ldg((const float4*)(hin + (long)c0.x * DIM + lane * 4));
        float4 v1 = __ldg((const float4*)(hin + (long)c1.x * DIM + lane * 4));
        float f0 = __int_as_float(c0.y), f1 = __int_as_float(c1.y);
        acc.x += v0.x * f0; acc.y += v0.y * f0; acc.z += v0.z * f0; acc.w += v0.w * f0;
        acc.x += v1.x * f1; acc.y += v1.y * f1; acc.z += v1.z * f1; acc.w += v1.w * f1;
    }
    if (e < end) {
        int2 c0 = g_csr[e];
        float4 v0 = __ldg((const float4*)(hin + (long)c0.x * DIM + lane * 4));
        float f0 = __int_as_float(c0.y);
        acc.x += v0.x * f0; acc.y += v0.y * f0; acc.z += v0.z * f0; acc.w += v0.w * f0;
    }
    *(float4*)(hout + (long)n * DIM + lane * 4) = acc;
}

// ---------------- FFN layer 1 (HMMA): hid = gelu(h @ w1^T + b1) ---------------
// CTA: 128 nodes x 128 j (blockIdx.y = j-half). Warp = 16 nodes x 128 j.
#define P1 136
#define F1_AH 0
#define F1_AL (128 * P1 * 2)
#define F1_BH (2 * 128 * P1 * 2)
#define F1_BL (3 * 128 * P1 * 2)
#define F1_SMEM (4 * 128 * P1 * 2)          // 139,264 B
__global__ void __launch_bounds__(256) ffn1_mma(const float* __restrict__ b1) {
    extern __shared__ char smem[];
    u32 sb = smem_u32(smem);
    int tid = threadIdx.x;
    int wid = tid >> 5, lane = tid & 31;
    int jhalf = blockIdx.y;
    long nbase = (long)blockIdx.x * 128;

    for (int idx = tid; idx < 128 * 16; idx += 256) {
        int row = idx >> 4, u = idx & 15;
        long n = nbase + row; if (n >= N_NODES) n = N_NODES - 1;
        *(uint4*)(smem + F1_AH + (row * P1 + u * 8) * 2) = *(const uint4*)(g_hhi + n * DIM + u * 8);
        *(uint4*)(smem + F1_AL + (row * P1 + u * 8) * 2) = *(const uint4*)(g_hlo + n * DIM + u * 8);
    }
    for (int idx = tid; idx < 128 * 16; idx += 256) {
        int row = idx >> 4, u = idx & 15;
        long jr = (long)jhalf * 128 + row;
        *(uint4*)(smem + F1_BH + (row * P1 + u * 8) * 2) = *(const uint4*)(g_w1h + jr * DIM + u * 8);
        *(uint4*)(smem + F1_BL + (row * P1 + u * 8) * 2) = *(const uint4*)(g_w1l + jr * DIM + u * 8);
    }
    __syncthreads();

    u32 a_row = (u32)(wid * 16 + (lane & 15));
    u32 a_col = (u32)((lane >> 4) * 8);
    u32 aH = sb + F1_AH + (a_row * P1 + a_col) * 2;
    u32 aL = sb + F1_AL + (a_row * P1 + a_col) * 2;
    u32 b_row = (u32)(lane & 7);
    u32 b_col = (u32)(((lane >> 3) & 1) * 8);
    u32 bH = sb + F1_BH + (b_row * P1 + b_col) * 2;
    u32 bL = sb + F1_BL + (b_row * P1 + b_col) * 2;

    float acc[16][4];
#pragma unroll
    for (int t = 0; t < 16; t++)
#pragma unroll
        for (int q = 0; q < 4; q++) acc[t][q] = 0.f;

#pragma unroll
    for (int ks = 0; ks < 8; ks++) {
        u32 ah[4], al[4];
        ldsm4(ah, aH + ks * 32);
        ldsm4(al, aL + ks * 32);
#pragma unroll
        for (int jt = 0; jt < 16; jt++) {
            u32 bh[2], bl[2];
            ldsm2(bh, bH + jt * (8 * P1 * 2) + ks * 32);
            ldsm2(bl, bL + jt * (8 * P1 * 2) + ks * 32);
            mma16816(acc[jt], ah, bh);
            mma16816(acc[jt], ah, bl);
            mma16816(acc[jt], al, bh);
        }
    }

    long n0 = nbase + wid * 16 + (lane >> 2);
    long n1 = n0 + 8;
    u32* ghi = (u32*)g_hidhi;
    u32* glo = (u32*)g_hidlo;
#pragma unroll
    for (int jt = 0; jt < 16; jt++) {
        int jg = jhalf * 128 + jt * 8 + (lane & 3) * 2;
        float bj0 = __ldg(&b1[jg]), bj1 = __ldg(&b1[jg + 1]);
#pragma unroll
        for (int half = 0; half < 2; half++) {
            long n = half ? n1 : n0;
            if (n < N_NODES) {
                float a0 = acc[jt][half * 2 + 0] + bj0;
                float a1 = acc[jt][half * 2 + 1] + bj1;
                float y0 = 0.5f * a0 * (1.0f + erff(a0 * 0.7071067811865476f));
                float y1 = 0.5f * a1 * (1.0f + erff(a1 * 0.7071067811865476f));
                __nv_bfloat16 h0 = __float2bfloat16(y0);
                __nv_bfloat16 h1 = __float2bfloat16(y1);
                __nv_bfloat16 l0 = __float2bfloat16(y0 - __bfloat162float(h0));
                __nv_bfloat16 l1 = __float2bfloat16(y1 - __bfloat162float(h1));
                __nv_bfloat162 ph; ph.x = h0; ph.y = h1;
                __nv_bfloat162 pl; pl.x = l0; pl.y = l1;
                ghi[n * (HID / 2) + (jg >> 1)] = *(u32*)&ph;
                glo[n * (HID / 2) + (jg >> 1)] = *(u32*)&pl;
            }
        }
    }
}

// ---------------- FFN layer 2 (HMMA): out = hid @ w2^T + b2 -------------------
#define P2 264
#define F2_AH 0
#define F2_AL (128 * P2 * 2)
#define F2_BH (2 * 128 * P2 * 2)
#define F2_BL (2 * 128 * P2 * 2 + 64 * P2 * 2)
#define F2_SMEM (2 * 128 * P2 * 2 + 2 * 64 * P2 * 2)   // 202,752 B
__global__ void __launch_bounds__(256) ffn2_mma(const float* __restrict__ b2,
                                                float* __restrict__ out) {
    extern __shared__ char smem[];
    u32 sb = smem_u32(smem);
    int tid = threadIdx.x;
    int wid = tid >> 5, lane = tid & 31;
    int jq = blockIdx.y;
    long nbase = (long)blockIdx.x * 128;

    for (int idx = tid; idx < 128 * 32; idx += 256) {
        int row = idx >> 5, u = idx & 31;
        long n = nbase + row; if (n >= N_NODES) n = N_NODES - 1;
        *(uint4*)(smem + F2_AH + (row * P2 + u * 8) * 2) = *(const uint4*)(g_hidhi + n * HID + u * 8);
        *(uint4*)(smem + F2_AL + (row * P2 + u * 8) * 2) = *(const uint4*)(g_hidlo + n * HID + u * 8);
    }
    for (int idx = tid; idx < 64 * 32; idx += 256) {
        int row = idx >> 5, u = idx & 31;
        long jr = (long)jq * 64 + row;
        *(uint4*)(smem + F2_BH + (row * P2 + u * 8) * 2) = *(const uint4*)(g_w2h + jr * HID + u * 8);
        *(uint4*)(smem + F2_BL + (row * P2 + u * 8) * 2) = *(const uint4*)(g_w2l + jr * HID + u * 8);
    }
    __syncthreads();

    u32 a_row = (u32)(wid * 16 + (lane & 15));
    u32 a_col = (u32)((lane >> 4) * 8);
    u32 aH = sb + F2_AH + (a_row * P2 + a_col) * 2;
    u32 aL = sb + F2_AL + (a_row * P2 + a_col) * 2;
    u32 b_row = (u32)(lane & 7);
    u32 b_col = (u32)(((lane >> 3) & 1) * 8);
    u32 bH = sb + F2_BH + (b_row * P2 + b_col) * 2;
    u32 bL = sb + F2_BL + (b_row * P2 + b_col) * 2;

    float acc[8][4];
#pragma unroll
    for (int t = 0; t < 8; t++)
#pragma unroll
        for (int q = 0; q < 4; q++) acc[t][q] = 0.f;

#pragma unroll
    for (int ks = 0; ks < 16; ks++) {
        u32 ah[4], al[4];
        ldsm4(ah, aH + ks * 32);
        ldsm4(al, aL + ks * 32);
#pragma unroll
        for (int jt = 0; jt < 8; jt++) {
            u32 bh[2], bl[2];
            ldsm2(bh, bH + jt * (8 * P2 * 2) + ks * 32);
            ldsm2(bl, bL + jt * (8 * P2 * 2) + ks * 32);
            mma16816(acc[jt], ah, bh);
            mma16816(acc[jt], ah, bl);
            mma16816(acc[jt], al, bh);
        }
    }

    long n0 = nbase + wid * 16 + (lane >> 2);
    long n1 = n0 + 8;
#pragma unroll
    for (int jt = 0; jt < 8; jt++) {
        int jg = jq * 64 + jt * 8 + (lane & 3) * 2;
        float bj0 = __ldg(&b2[jg]), bj1 = __ldg(&b2[jg + 1]);
        if (n0 < N_NODES) {
            float2 v = make_float2(acc[jt][0] + bj0, acc[jt][1] + bj1);
            *(float2*)(out + n0 * DIM + jg) = v;
        }
        if (n1 < N_NODES) {
            float2 v = make_float2(acc[jt][2] + bj0, acc[jt][3] + bj1);
            *(float2*)(out + n1 * DIM + jg) = v;
        }
    }
}

// ---------------- launch ----------------------------------------------------
extern "C" void kernel_launch(void* const* d_in, const int* in_sizes, int n_in,
                              void* d_out, int out_size) {
    const float* x   = (const float*)d_in[0];
    const float* rep = (const float*)d_in[1];
    const int*   src = (const int*)d_in[2];
    const int*   dst = (const int*)d_in[3];
    const float* w1  = (const float*)d_in[4];
    const float* b1  = (const float*)d_in[5];
    const float* w2  = (const float*)d_in[6];
    const float* b2  = (const float*)d_in[7];
    float* out = (float*)d_out;

    static int smem_set = 0;
    if (!smem_set) {
        cudaFuncSetAttribute(ffn1_mma, cudaFuncAttributeMaxDynamicSharedMemorySize, F1_SMEM);
        cudaFuncSetAttribute(ffn2_mma, cudaFuncAttributeMaxDynamicSharedMemorySize, F2_SMEM);
        smem_set = 1;
    }

    float *ha, *hb;
    __nv_bfloat16 *hhi, *hlo;
    cudaGetSymbolAddress((void**)&ha,  g_ha);
    cudaGetSymbolAddress((void**)&hb,  g_hb);
    cudaGetSymbolAddress((void**)&hhi, g_hhi);
    cudaGetSymbolAddress((void**)&hlo, g_hlo);

    // CSR build
    init_kernel<<<(N_NODES + 255) / 256, 256>>>(src);
    deg_hist_kernel<<<N_EDGES / 256, 256>>>(src, dst);
    scan_a_kernel<<<SCAN_B, 1024>>>();
    scan_c_kernel<<<SCAN_B, 1024>>>();
    fill_kernel<<<N_EDGES / 256, 256>>>(src, dst);

    // weight split
    wsplit_kernel<<<(2 * HID * DIM + 255) / 256, 256>>>(w1, w2);

    // forward rotation x -> ha
    rot_kernel<<<(N_NODES * DIM) / 256, 256>>>(x, rep, ha);

    // message passing: ha -> hb -> ha
    gather_kernel<<<(N_NODES * 32) / 256, 256>>>(ha, hb);
    gather_kernel<<<(N_NODES * 32) / 256, 256>>>(hb, ha);

    // inverse rotation -> bf16 hi/lo
    rot_t_split_kernel<<<(N_NODES * DIM) / 256, 256>>>(ha, rep, hhi, hlo);

    // tensor-core FFN (warp MMA)
    int tiles = (N_NODES + 127) / 128;
    dim3 g1(tiles, 2), g2(tiles, 2);
    ffn1_mma<<<g1, 256, F1_SMEM>>>(b1);
    ffn2_mma<<<g2, 256, F2_SMEM>>>(b2, out);
}

// round 9
// speedup vs baseline: 3.4579x; 1.0032x over previous
#include <cuda_runtime.h>
#include <cuda_bf16.h>

#define N_NODES 100000
#define N_EDGES 1600000
#define DIM 128
#define HID 256
#define SCAN_B 98

typedef unsigned long long u64;
typedef unsigned int u32;

// ---------------- scratch (static device globals; no allocs allowed) --------
__device__ float g_deg[N_NODES];
__device__ int   g_cnt[N_NODES];
__device__ int   g_part[SCAN_B];
__device__ int   g_row[N_NODES + 1];
__device__ int   g_fill[N_NODES];
__device__ int2  g_csr[N_EDGES];
__device__ float g_ha[N_NODES * DIM];
__device__ float g_hb[N_NODES * DIM];
__device__ __nv_bfloat16 g_hidhi[(long)N_NODES * HID];
__device__ __nv_bfloat16 g_hidlo[(long)N_NODES * HID];
__device__ __nv_bfloat16 g_w1h[HID * DIM], g_w1l[HID * DIM];
__device__ __nv_bfloat16 g_w2h[DIM * HID], g_w2l[DIM * HID];
__device__ int   g_sh;

// ---------------- warp-MMA helpers ------------------------------------------
__device__ __forceinline__ u32 smem_u32(const void* p) {
    u32 a;
    asm("{ .reg .u64 t; cvta.to.shared.u64 t, %1; cvt.u32.u64 %0, t; }" : "=r"(a) : "l"(p));
    return a;
}
__device__ __forceinline__ void ldsm4(u32* r, u32 a) {
    asm volatile("ldmatrix.sync.aligned.m8n8.x4.shared.b16 {%0,%1,%2,%3}, [%4];"
                 : "=r"(r[0]), "=r"(r[1]), "=r"(r[2]), "=r"(r[3]) : "r"(a));
}
__device__ __forceinline__ void mma16816(float* c, const u32* a, const u32* b) {
    asm volatile("mma.sync.aligned.m16n8k16.row.col.f32.bf16.bf16.f32 "
                 "{%0,%1,%2,%3}, {%4,%5,%6,%7}, {%8,%9}, {%0,%1,%2,%3};"
                 : "+f"(c[0]), "+f"(c[1]), "+f"(c[2]), "+f"(c[3])
                 : "r"(a[0]), "r"(a[1]), "r"(a[2]), "r"(a[3]), "r"(b[0]), "r"(b[1]));
}
__device__ __forceinline__ void bsplit(float v, __nv_bfloat16& hi, __nv_bfloat16& lo) {
    hi = __float2bfloat16(v);
    lo = __float2bfloat16(v - __bfloat162float(hi));
}

// ---------------- init / CSR build ------------------------------------------
__global__ void init_kernel(const int* __restrict__ src) {
    int i = blockIdx.x * blockDim.x + threadIdx.x;
    if (i < N_NODES) { g_deg[i] = 0.f; g_cnt[i] = 0; }
    if (i == 0) g_sh = (src[1] == 0 && src[2] == 1) ? 1 : 0;
}

__global__ void deg_hist_kernel(const int* __restrict__ src, const int* __restrict__ dst) {
    int e = blockIdx.x * blockDim.x + threadIdx.x;
    if (e < N_EDGES) {
        int sh = g_sh;
        atomicAdd(&g_deg[src[(long)e << sh]], 1.0f);
        atomicAdd(&g_cnt[dst[(long)e << sh]], 1);
    }
}

__global__ void scan_a_kernel() {
    __shared__ int s[1024];
    int t = threadIdx.x;
    int i = blockIdx.x * 1024 + t;
    s[t] = (i < N_NODES) ? g_cnt[i] : 0;
    __syncthreads();
    for (int off = 512; off > 0; off >>= 1) {
        if (t < off) s[t] += s[t + off];
        __syncthreads();
    }
    if (t == 0) g_part[blockIdx.x] = s[0];
}

__global__ void scan_c_kernel() {
    __shared__ int s[1024];
    __shared__ int base_s;
    int t = threadIdx.x;
    int b = blockIdx.x;
    int i = b * 1024 + t;
    int v = (i < N_NODES) ? g_cnt[i] : 0;
    s[t] = v;
    if (t == 0) {
        int base = 0;
        for (int k = 0; k < b; k++) base += g_part[k];
        base_s = base;
    }
    __syncthreads();
    for (int off = 1; off < 1024; off <<= 1) {
        int add = (t >= off) ? s[t - off] : 0;
        __syncthreads();
        s[t] += add;
        __syncthreads();
    }
    int base = base_s;
    if (i < N_NODES) {
        int excl = base + s[t] - v;
        g_row[i] = excl;
        g_fill[i] = excl;
        if (i == N_NODES - 1) g_row[N_NODES] = base + s[t];
    }
}

__global__ void fill_kernel(const int* __restrict__ src, const int* __restrict__ dst) {
    int e = blockIdx.x * blockDim.x + threadIdx.x;
    if (e < N_EDGES) {
        int sh = g_sh;
        int s = src[(long)e << sh];
        int d = dst[(long)e << sh];
        float c = rsqrtf(g_deg[s] * g_deg[d]);
        int pos = atomicAdd(&g_fill[d], 1);
        g_csr[pos] = make_int2(s, __float_as_int(c));
    }
}

// ---------------- forward rotation -------------------------------------------
__global__ void rot_kernel(const float* __restrict__ x, const float* __restrict__ rep,
                           float* __restrict__ out) {
    int i = blockIdx.x * blockDim.x + threadIdx.x;
    int n = i >> 7;
    int t = i & 127;
    int b = t >> 4, c = (t >> 2) & 3, el = t & 3;
    float4 r = *(const float4*)(rep + (((long)n * 8 + b) * 16 + c * 4));
    const float* xb = x + (long)n * DIM + b * 16 + el;
    out[i] = r.x * xb[0] + r.y * xb[4] + r.z * xb[8] + r.w * xb[12];
}

__global__ void wsplit_kernel(const float* __restrict__ w1, const float* __restrict__ w2) {
    int i = blockIdx.x * blockDim.x + threadIdx.x;
    if (i < HID * DIM) {
        bsplit(w1[i], g_w1h[i], g_w1l[i]);
    } else if (i < 2 * HID * DIM) {
        int j = i - HID * DIM;
        bsplit(w2[j], g_w2h[j], g_w2l[j]);
    }
}

// ---------------- gather ------------------------------------------------------
__global__ void gather_kernel(const float* __restrict__ hin, float* __restrict__ hout) {
    int gid = blockIdx.x * blockDim.x + threadIdx.x;
    int n = gid >> 5;
    int lane = gid & 31;
    int beg = g_row[n], end = g_row[n + 1];
    float4 acc = make_float4(0.f, 0.f, 0.f, 0.f);
    int e = beg;
    for (; e + 2 <= end; e += 2) {
        int2 c0 = g_csr[e];
        int2 c1 = g_csr[e + 1];
        float4 v0 = __ldg((const float4*)(hin + (long)c0.x * DIM + lane * 4));
        float4 v1 = __ldg((const float4*)(hin + (long)c1.x * DIM + lane * 4));
        float f0 = __int_as_float(c0.y), f1 = __int_as_float(c1.y);
        acc.x += v0.x * f0; acc.y += v0.y * f0; acc.z += v0.z * f0; acc.w += v0.w * f0;
        acc.x += v1.x * f1; acc.y += v1.y * f1; acc.z += v1.z * f1; acc.w += v1.w * f1;
    }
    if (e < end) {
        int2 c0 = g_csr[e];
        float4 v0 = __ldg((const float4*)(hin + (long)c0.x * DIM + lane * 4));
        float f0 = __int_as_float(c0.y);
        acc.x += v0.x * f0; acc.y += v0.y * f0; acc.z += v0.z * f0; acc.w += v0.w * f0;
    }
    *(float4*)(hout + (long)n * DIM + lane * 4) = acc;
}

// ---------------- FFN layer 1 (HMMA, fused inverse rotation) ------------------
// CTA: 128 nodes x 128 j (blockIdx.y = j-half). A-staging applies the
// transposed bundle rotation to the fp32 gather output and splits to bf16 hi/lo.
#define P1 136
#define F1_AH 0
#define F1_AL (128 * P1 * 2)
#define F1_BH (2 * 128 * P1 * 2)
#define F1_BL (3 * 128 * P1 * 2)
#define F1_SMEM (4 * 128 * P1 * 2)          // 139,264 B
__global__ void __launch_bounds__(256) ffn1_mma(const float* __restrict__ rep,
                                                const float* __restrict__ b1) {
    extern __shared__ char smem[];
    u32 sb = smem_u32(smem);
    int tid = threadIdx.x;
    int wid = tid >> 5, lane = tid & 31;
    int jhalf = blockIdx.y;
    long nbase = (long)blockIdx.x * 128;

    // stage A: rot_t(g_ha) split to hi/lo. Thread handles elements u*8..u*8+7
    // of row: bundle b = u>>1, c-groups {c0, c0+1} with c0 = (u&1)*2.
    for (int idx = tid; idx < 128 * 16; idx += 256) {
        int row = idx >> 4, u = idx & 15;
        long n = nbase + row; if (n >= N_NODES) n = N_NODES - 1;
        int b = u >> 1;
        const float4* hv = (const float4*)(g_ha + n * DIM + b * 16);
        float4 q0 = hv[0], q1 = hv[1], q2 = hv[2], q3 = hv[3];       // q_d[e]
        const float4* rv = (const float4*)(rep + ((long)n * 8 + b) * 16);
        float4 R0 = rv[0], R1 = rv[1], R2 = rv[2], R3 = rv[3];       // R_d[c]
        float rc[2][4];
        if (u & 1) {  // c = 2, 3
            rc[0][0] = R0.z; rc[0][1] = R1.z; rc[0][2] = R2.z; rc[0][3] = R3.z;
            rc[1][0] = R0.w; rc[1][1] = R1.w; rc[1][2] = R2.w; rc[1][3] = R3.w;
        } else {      // c = 0, 1
            rc[0][0] = R0.x; rc[0][1] = R1.x; rc[0][2] = R2.x; rc[0][3] = R3.x;
            rc[1][0] = R0.y; rc[1][1] = R1.y; rc[1][2] = R2.y; rc[1][3] = R3.y;
        }
        __nv_bfloat16 hi[8], lo[8];
#pragma unroll
        for (int cc = 0; cc < 2; cc++) {
            float v0 = rc[cc][0] * q0.x + rc[cc][1] * q1.x + rc[cc][2] * q2.x + rc[cc][3] * q3.x;
            float v1 = rc[cc][0] * q0.y + rc[cc][1] * q1.y + rc[cc][2] * q2.y + rc[cc][3] * q3.y;
            float v2 = rc[cc][0] * q0.z + rc[cc][1] * q1.z + rc[cc][2] * q2.z + rc[cc][3] * q3.z;
            float v3 = rc[cc][0] * q0.w + rc[cc][1] * q1.w + rc[cc][2] * q2.w + rc[cc][3] * q3.w;
            bsplit(v0, hi[cc * 4 + 0], lo[cc * 4 + 0]);
            bsplit(v1, hi[cc * 4 + 1], lo[cc * 4 + 1]);
            bsplit(v2, hi[cc * 4 + 2], lo[cc * 4 + 2]);
            bsplit(v3, hi[cc * 4 + 3], lo[cc * 4 + 3]);
        }
        *(uint4*)(smem + F1_AH + (row * P1 + u * 8) * 2) = *(uint4*)hi;
        *(uint4*)(smem + F1_AL + (row * P1 + u * 8) * 2) = *(uint4*)lo;
    }
    // stage B (w1 half): 128 j-rows x 128 k
    for (int idx = tid; idx < 128 * 16; idx += 256) {
        int row = idx >> 4, u = idx & 15;
        long jr = (long)jhalf * 128 + row;
        *(uint4*)(smem + F1_BH + (row * P1 + u * 8) * 2) = *(const uint4*)(g_w1h + jr * DIM + u * 8);
        *(uint4*)(smem + F1_BL + (row * P1 + u * 8) * 2) = *(const uint4*)(g_w1l + jr * DIM + u * 8);
    }
    __syncthreads();

    u32 a_row = (u32)(wid * 16 + (lane & 15));
    u32 a_col = (u32)((lane >> 4) * 8);
    u32 aH = sb + F1_AH + (a_row * P1 + a_col) * 2;
    u32 aL = sb + F1_AL + (a_row * P1 + a_col) * 2;
    // B via ldsm4: lane group g = lane>>3; mats: (jrow+0..7|+8..15) x (k|k+8)
    int g = lane >> 3;
    u32 brow = (u32)((g >> 1) * 8 + (lane & 7));
    u32 bcol = (u32)((g & 1) * 8);
    u32 bH4 = sb + F1_BH + (brow * P1 + bcol) * 2;
    u32 bL4 = sb + F1_BL + (brow * P1 + bcol) * 2;

    float acc[16][4];
#pragma unroll
    for (int t = 0; t < 16; t++)
#pragma unroll
        for (int q = 0; q < 4; q++) acc[t][q] = 0.f;

#pragma unroll
    for (int ks = 0; ks < 8; ks++) {
        u32 ah[4], al[4];
        ldsm4(ah, aH + ks * 32);
        ldsm4(al, aL + ks * 32);
#pragma unroll
        for (int jp = 0; jp < 8; jp++) {
            u32 bh[4], bl[4];
            ldsm4(bh, bH4 + jp * (16 * P1 * 2) + ks * 32);
            ldsm4(bl, bL4 + jp * (16 * P1 * 2) + ks * 32);
            mma16816(acc[2 * jp],     ah, &bh[0]);
            mma16816(acc[2 * jp],     ah, &bl[0]);
            mma16816(acc[2 * jp],     al, &bh[0]);
            mma16816(acc[2 * jp + 1], ah, &bh[2]);
            mma16816(acc[2 * jp + 1], ah, &bl[2]);
            mma16816(acc[2 * jp + 1], al, &bh[2]);
        }
    }

    long n0 = nbase + wid * 16 + (lane >> 2);
    long n1 = n0 + 8;
    u32* ghi = (u32*)g_hidhi;
    u32* glo = (u32*)g_hidlo;
#pragma unroll
    for (int jt = 0; jt < 16; jt++) {
        int jg = jhalf * 128 + jt * 8 + (lane & 3) * 2;
        float bj0 = __ldg(&b1[jg]), bj1 = __ldg(&b1[jg + 1]);
#pragma unroll
        for (int half = 0; half < 2; half++) {
            long n = half ? n1 : n0;
            if (n < N_NODES) {
                float a0 = acc[jt][half * 2 + 0] + bj0;
                float a1 = acc[jt][half * 2 + 1] + bj1;
                float y0 = 0.5f * a0 * (1.0f + erff(a0 * 0.7071067811865476f));
                float y1 = 0.5f * a1 * (1.0f + erff(a1 * 0.7071067811865476f));
                __nv_bfloat162 ph, pl;
                bsplit(y0, ph.x, pl.x);
                bsplit(y1, ph.y, pl.y);
                ghi[n * (HID / 2) + (jg >> 1)] = *(u32*)&ph;
                glo[n * (HID / 2) + (jg >> 1)] = *(u32*)&pl;
            }
        }
    }
}

// ---------------- FFN layer 2 (HMMA): out = hid @ w2^T + b2 -------------------
#define P2 264
#define F2_AH 0
#define F2_AL (128 * P2 * 2)
#define F2_BH (2 * 128 * P2 * 2)
#define F2_BL (2 * 128 * P2 * 2 + 64 * P2 * 2)
#define F2_SMEM (2 * 128 * P2 * 2 + 2 * 64 * P2 * 2)   // 202,752 B
__global__ void __launch_bounds__(256) ffn2_mma(const float* __restrict__ b2,
                                                float* __restrict__ out) {
    extern __shared__ char smem[];
    u32 sb = smem_u32(smem);
    int tid = threadIdx.x;
    int wid = tid >> 5, lane = tid & 31;
    int jq = blockIdx.y;
    long nbase = (long)blockIdx.x * 128;

    for (int idx = tid; idx < 128 * 32; idx += 256) {
        int row = idx >> 5, u = idx & 31;
        long n = nbase + row; if (n >= N_NODES) n = N_NODES - 1;
        *(uint4*)(smem + F2_AH + (row * P2 + u * 8) * 2) = *(const uint4*)(g_hidhi + n * HID + u * 8);
        *(uint4*)(smem + F2_AL + (row * P2 + u * 8) * 2) = *(const uint4*)(g_hidlo + n * HID + u * 8);
    }
    for (int idx = tid; idx < 64 * 32; idx += 256) {
        int row = idx >> 5, u = idx & 31;
        long jr = (long)jq * 64 + row;
        *(uint4*)(smem + F2_BH + (row * P2 + u * 8) * 2) = *(const uint4*)(g_w2h + jr * HID + u * 8);
        *(uint4*)(smem + F2_BL + (row * P2 + u * 8) * 2) = *(const uint4*)(g_w2l + jr * HID + u * 8);
    }
    __syncthreads();

    u32 a_row = (u32)(wid * 16 + (lane & 15));
    u32 a_col = (u32)((lane >> 4) * 8);
    u32 aH = sb + F2_AH + (a_row * P2 + a_col) * 2;
    u32 aL = sb + F2_AL + (a_row * P2 + a_col) * 2;
    int g = lane >> 3;
    u32 brow = (u32)((g >> 1) * 8 + (lane & 7));
    u32 bcol = (u32)((g & 1) * 8);
    u32 bH4 = sb + F2_BH + (brow * P2 + bcol) * 2;
    u32 bL4 = sb + F2_BL + (brow * P2 + bcol) * 2;

    float acc[8][4];
#pragma unroll
    for (int t = 0; t < 8; t++)
#pragma unroll
        for (int q = 0; q < 4; q++) acc[t][q] = 0.f;

#pragma unroll
    for (int ks = 0; ks < 16; ks++) {
        u32 ah[4], al[4];
        ldsm4(ah, aH + ks * 32);
        ldsm4(al, aL + ks * 32);
#pragma unroll
        for (int jp = 0; jp < 4; jp++) {
            u32 bh[4], bl[4];
            ldsm4(bh, bH4 + jp * (16 * P2 * 2) + ks * 32);
            ldsm4(bl, bL4 + jp * (16 * P2 * 2) + ks * 32);
            mma16816(acc[2 * jp],     ah, &bh[0]);
            mma16816(acc[2 * jp],     ah, &bl[0]);
            mma16816(acc[2 * jp],     al, &bh[0]);
            mma16816(acc[2 * jp + 1], ah, &bh[2]);
            mma16816(acc[2 * jp + 1], ah, &bl[2]);
            mma16816(acc[2 * jp + 1], al, &bh[2]);
        }
    }

    long n0 = nbase + wid * 16 + (lane >> 2);
    long n1 = n0 + 8;
#pragma unroll
    for (int jt = 0; jt < 8; jt++) {
        int jg = jq * 64 + jt * 8 + (lane & 3) * 2;
        float bj0 = __ldg(&b2[jg]), bj1 = __ldg(&b2[jg + 1]);
        if (n0 < N_NODES) {
            float2 v = make_float2(acc[jt][0] + bj0, acc[jt][1] + bj1);
            *(float2*)(out + n0 * DIM + jg) = v;
        }
        if (n1 < N_NODES) {
            float2 v = make_float2(acc[jt][2] + bj0, acc[jt][3] + bj1);
            *(float2*)(out + n1 * DIM + jg) = v;
        }
    }
}

// ---------------- launch ----------------------------------------------------
extern "C" void kernel_launch(void* const* d_in, const int* in_sizes, int n_in,
                              void* d_out, int out_size) {
    const float* x   = (const float*)d_in[0];
    const float* rep = (const float*)d_in[1];
    const int*   src = (const int*)d_in[2];
    const int*   dst = (const int*)d_in[3];
    const float* w1  = (const float*)d_in[4];
    const float* b1  = (const float*)d_in[5];
    const float* w2  = (const float*)d_in[6];
    const float* b2  = (const float*)d_in[7];
    float* out = (float*)d_out;

    static int smem_set = 0;
    if (!smem_set) {
        cudaFuncSetAttribute(ffn1_mma, cudaFuncAttributeMaxDynamicSharedMemorySize, F1_SMEM);
        cudaFuncSetAttribute(ffn2_mma, cudaFuncAttributeMaxDynamicSharedMemorySize, F2_SMEM);
        smem_set = 1;
    }

    float *ha, *hb;
    cudaGetSymbolAddress((void**)&ha, g_ha);
    cudaGetSymbolAddress((void**)&hb, g_hb);

    // CSR build
    init_kernel<<<(N_NODES + 255) / 256, 256>>>(src);
    deg_hist_kernel<<<N_EDGES / 256, 256>>>(src, dst);
    scan_a_kernel<<<SCAN_B, 1024>>>();
    scan_c_kernel<<<SCAN_B, 1024>>>();
    fill_kernel<<<N_EDGES / 256, 256>>>(src, dst);

    // weight split
    wsplit_kernel<<<(2 * HID * DIM + 255) / 256, 256>>>(w1, w2);

    // forward rotation x -> ha
    rot_kernel<<<(N_NODES * DIM) / 256, 256>>>(x, rep, ha);

    // message passing: ha -> hb -> ha
    gather_kernel<<<(N_NODES * 32) / 256, 256>>>(ha, hb);
    gather_kernel<<<(N_NODES * 32) / 256, 256>>>(hb, ha);

    // FFN (inverse rotation fused into ffn1 A-staging)
    int tiles = (N_NODES + 127) / 128;
    dim3 g1(tiles, 2), g2(tiles, 2);
    ffn1_mma<<<g1, 256, F1_SMEM>>>(rep, b1);
    ffn2_mma<<<g2, 256, F2_SMEM>>>(b2, out);
}

// round 10
// speedup vs baseline: 4.6305x; 1.3391x over previous
#include <cuda_runtime.h>
#include <cuda_bf16.h>

#define N_NODES 100000
#define N_EDGES 1600000
#define DIM 128
#define HID 256
#define SCAN_B 98

typedef unsigned long long u64;
typedef unsigned int u32;

// ---------------- scratch (static device globals; no allocs allowed) --------
__device__ float g_deg[N_NODES];
__device__ int   g_cnt[N_NODES];
__device__ int   g_part[SCAN_B];
__device__ int   g_row[N_NODES + 1];
__device__ int   g_fill[N_NODES];
__device__ int2  g_csr[N_EDGES];
__device__ float g_ha[N_NODES * DIM];
__device__ float g_hb[N_NODES * DIM];
__device__ __nv_bfloat16 g_hidhi[(long)N_NODES * HID];
__device__ __nv_bfloat16 g_hidlo[(long)N_NODES * HID];
__device__ __nv_bfloat16 g_w1h[HID * DIM], g_w1l[HID * DIM];
__device__ __nv_bfloat16 g_w2h[DIM * HID], g_w2l[DIM * HID];
__device__ int   g_sh;

// ---------------- warp-MMA helpers ------------------------------------------
__device__ __forceinline__ u32 smem_u32(const void* p) {
    u32 a;
    asm("{ .reg .u64 t; cvta.to.shared.u64 t, %1; cvt.u32.u64 %0, t; }" : "=r"(a) : "l"(p));
    return a;
}
__device__ __forceinline__ void ldsm4(u32* r, u32 a) {
    asm volatile("ldmatrix.sync.aligned.m8n8.x4.shared.b16 {%0,%1,%2,%3}, [%4];"
                 : "=r"(r[0]), "=r"(r[1]), "=r"(r[2]), "=r"(r[3]) : "r"(a));
}
__device__ __forceinline__ void mma16816(float* c, const u32* a, const u32* b) {
    asm volatile("mma.sync.aligned.m16n8k16.row.col.f32.bf16.bf16.f32 "
                 "{%0,%1,%2,%3}, {%4,%5,%6,%7}, {%8,%9}, {%0,%1,%2,%3};"
                 : "+f"(c[0]), "+f"(c[1]), "+f"(c[2]), "+f"(c[3])
                 : "r"(a[0]), "r"(a[1]), "r"(a[2]), "r"(a[3]), "r"(b[0]), "r"(b[1]));
}
__device__ __forceinline__ void bsplit(float v, __nv_bfloat16& hi, __nv_bfloat16& lo) {
    hi = __float2bfloat16(v);
    lo = __float2bfloat16(v - __bfloat162float(hi));
}

// ---------------- init / CSR build ------------------------------------------
__global__ void init_kernel(const int* __restrict__ src) {
    int i = blockIdx.x * blockDim.x + threadIdx.x;
    if (i < N_NODES) { g_deg[i] = 0.f; g_cnt[i] = 0; }
    if (i == 0) g_sh = (src[1] == 0 && src[2] == 1) ? 1 : 0;
}

__global__ void deg_hist_kernel(const int* __restrict__ src, const int* __restrict__ dst) {
    int e = blockIdx.x * blockDim.x + threadIdx.x;
    if (e < N_EDGES) {
        int sh = g_sh;
        atomicAdd(&g_deg[src[(long)e << sh]], 1.0f);
        atomicAdd(&g_cnt[dst[(long)e << sh]], 1);
    }
}

__global__ void scan_a_kernel() {
    __shared__ int s[1024];
    int t = threadIdx.x;
    int i = blockIdx.x * 1024 + t;
    s[t] = (i < N_NODES) ? g_cnt[i] : 0;
    __syncthreads();
    for (int off = 512; off > 0; off >>= 1) {
        if (t < off) s[t] += s[t + off];
        __syncthreads();
    }
    if (t == 0) g_part[blockIdx.x] = s[0];
}

__global__ void scan_c_kernel() {
    __shared__ int s[1024];
    __shared__ int base_s;
    int t = threadIdx.x;
    int b = blockIdx.x;
    int i = b * 1024 + t;
    int v = (i < N_NODES) ? g_cnt[i] : 0;
    s[t] = v;
    if (t == 0) {
        int base = 0;
        for (int k = 0; k < b; k++) base += g_part[k];
        base_s = base;
    }
    __syncthreads();
    for (int off = 1; off < 1024; off <<= 1) {
        int add = (t >= off) ? s[t - off] : 0;
        __syncthreads();
        s[t] += add;
        __syncthreads();
    }
    int base = base_s;
    if (i < N_NODES) {
        int excl = base + s[t] - v;
        g_row[i] = excl;
        g_fill[i] = excl;
        if (i == N_NODES - 1) g_row[N_NODES] = base + s[t];
    }
}

__global__ void fill_kernel(const int* __restrict__ src, const int* __restrict__ dst) {
    int e = blockIdx.x * blockDim.x + threadIdx.x;
    if (e < N_EDGES) {
        int sh = g_sh;
        int s = src[(long)e << sh];
        int d = dst[(long)e << sh];
        float c = rsqrtf(g_deg[s] * g_deg[d]);
        int pos = atomicAdd(&g_fill[d], 1);
        g_csr[pos] = make_int2(s, __float_as_int(c));
    }
}

// ---------------- forward rotation -------------------------------------------
__global__ void rot_kernel(const float* __restrict__ x, const float* __restrict__ rep,
                           float* __restrict__ out) {
    int i = blockIdx.x * blockDim.x + threadIdx.x;
    int n = i >> 7;
    int t = i & 127;
    int b = t >> 4, c = (t >> 2) & 3, el = t & 3;
    float4 r = *(const float4*)(rep + (((long)n * 8 + b) * 16 + c * 4));
    const float* xb = x + (long)n * DIM + b * 16 + el;
    out[i] = r.x * xb[0] + r.y * xb[4] + r.z * xb[8] + r.w * xb[12];
}

__global__ void wsplit_kernel(const float* __restrict__ w1, const float* __restrict__ w2) {
    int i = blockIdx.x * blockDim.x + threadIdx.x;
    if (i < HID * DIM) {
        bsplit(w1[i], g_w1h[i], g_w1l[i]);
    } else if (i < 2 * HID * DIM) {
        int j = i - HID * DIM;
        bsplit(w2[j], g_w2h[j], g_w2l[j]);
    }
}

// ---------------- gather ------------------------------------------------------
__global__ void gather_kernel(const float* __restrict__ hin, float* __restrict__ hout) {
    int gid = blockIdx.x * blockDim.x + threadIdx.x;
    int n = gid >> 5;
    int lane = gid & 31;
    int beg = g_row[n], end = g_row[n + 1];
    float4 acc = make_float4(0.f, 0.f, 0.f, 0.f);
    int e = beg;
    for (; e + 2 <= end; e += 2) {
        int2 c0 = g_csr[e];
        int2 c1 = g_csr[e + 1];
        float4 v0 = __ldg((const float4*)(hin + (long)c0.x * DIM + lane * 4));
        float4 v1 = __ldg((const float4*)(hin + (long)c1.x * DIM + lane * 4));
        float f0 = __int_as_float(c0.y), f1 = __int_as_float(c1.y);
        acc.x += v0.x * f0; acc.y += v0.y * f0; acc.z += v0.z * f0; acc.w += v0.w * f0;
        acc.x += v1.x * f1; acc.y += v1.y * f1; acc.z += v1.z * f1; acc.w += v1.w * f1;
    }
    if (e < end) {
        int2 c0 = g_csr[e];
        float4 v0 = __ldg((const float4*)(hin + (long)c0.x * DIM + lane * 4));
        float f0 = __int_as_float(c0.y);
        acc.x += v0.x * f0; acc.y += v0.y * f0; acc.z += v0.z * f0; acc.w += v0.w * f0;
    }
    *(float4*)(hout + (long)n * DIM + lane * 4) = acc;
}

// ---------------- FFN layer 1 (HMMA, fused inverse rotation, 2 CTA/SM) --------
// CTA: 128 nodes x 128 j (blockIdx.y = j-half). A resident full-K; B staged in
// two K=64 chunks so smem fits 2 CTAs/SM.
#define P1  136          // A row stride (full K=128 + pad)
#define PB1 72           // B chunk row stride (K=64 + pad)
#define F1_AH 0
#define F1_AL (128 * P1 * 2)
#define F1_BH (2 * 128 * P1 * 2)
#define F1_BL (2 * 128 * P1 * 2 + 128 * PB1 * 2)
#define F1_SMEM (2 * 128 * P1 * 2 + 2 * 128 * PB1 * 2)   // 106,496 B
__global__ void __launch_bounds__(256, 2) ffn1_mma(const float* __restrict__ rep,
                                                   const float* __restrict__ b1) {
    extern __shared__ char smem[];
    u32 sb = smem_u32(smem);
    int tid = threadIdx.x;
    int wid = tid >> 5, lane = tid & 31;
    int jhalf = blockIdx.y;
    long nbase = (long)blockIdx.x * 128;

    // stage A: rot_t(g_ha) split to hi/lo (full K)
    for (int idx = tid; idx < 128 * 16; idx += 256) {
        int row = idx >> 4, u = idx & 15;
        long n = nbase + row; if (n >= N_NODES) n = N_NODES - 1;
        int b = u >> 1;
        const float4* hv = (const float4*)(g_ha + n * DIM + b * 16);
        float4 q0 = hv[0], q1 = hv[1], q2 = hv[2], q3 = hv[3];
        const float4* rv = (const float4*)(rep + ((long)n * 8 + b) * 16);
        float4 R0 = rv[0], R1 = rv[1], R2 = rv[2], R3 = rv[3];
        float rc[2][4];
        if (u & 1) {
            rc[0][0] = R0.z; rc[0][1] = R1.z; rc[0][2] = R2.z; rc[0][3] = R3.z;
            rc[1][0] = R0.w; rc[1][1] = R1.w; rc[1][2] = R2.w; rc[1][3] = R3.w;
        } else {
            rc[0][0] = R0.x; rc[0][1] = R1.x; rc[0][2] = R2.x; rc[0][3] = R3.x;
            rc[1][0] = R0.y; rc[1][1] = R1.y; rc[1][2] = R2.y; rc[1][3] = R3.y;
        }
        __nv_bfloat16 hi[8], lo[8];
#pragma unroll
        for (int cc = 0; cc < 2; cc++) {
            float v0 = rc[cc][0] * q0.x + rc[cc][1] * q1.x + rc[cc][2] * q2.x + rc[cc][3] * q3.x;
            float v1 = rc[cc][0] * q0.y + rc[cc][1] * q1.y + rc[cc][2] * q2.y + rc[cc][3] * q3.y;
            float v2 = rc[cc][0] * q0.z + rc[cc][1] * q1.z + rc[cc][2] * q2.z + rc[cc][3] * q3.z;
            float v3 = rc[cc][0] * q0.w + rc[cc][1] * q1.w + rc[cc][2] * q2.w + rc[cc][3] * q3.w;
            bsplit(v0, hi[cc * 4 + 0], lo[cc * 4 + 0]);
            bsplit(v1, hi[cc * 4 + 1], lo[cc * 4 + 1]);
            bsplit(v2, hi[cc * 4 + 2], lo[cc * 4 + 2]);
            bsplit(v3, hi[cc * 4 + 3], lo[cc * 4 + 3]);
        }
        *(uint4*)(smem + F1_AH + (row * P1 + u * 8) * 2) = *(uint4*)hi;
        *(uint4*)(smem + F1_AL + (row * P1 + u * 8) * 2) = *(uint4*)lo;
    }

    u32 a_row = (u32)(wid * 16 + (lane & 15));
    u32 a_col = (u32)((lane >> 4) * 8);
    u32 aH = sb + F1_AH + (a_row * P1 + a_col) * 2;
    u32 aL = sb + F1_AL + (a_row * P1 + a_col) * 2;
    int g = lane >> 3;
    u32 brow = (u32)((g >> 1) * 8 + (lane & 7));
    u32 bcol = (u32)((g & 1) * 8);
    u32 bH4 = sb + F1_BH + (brow * PB1 + bcol) * 2;
    u32 bL4 = sb + F1_BL + (brow * PB1 + bcol) * 2;

    float acc[16][4];
#pragma unroll
    for (int t = 0; t < 16; t++)
#pragma unroll
        for (int q = 0; q < 4; q++) acc[t][q] = 0.f;

#pragma unroll
    for (int kc = 0; kc < 2; kc++) {
        // stage B chunk: 128 j-rows x 64 k
        for (int idx = tid; idx < 128 * 8; idx += 256) {
            int row = idx >> 3, u = idx & 7;
            long jr = (long)jhalf * 128 + row;
            long koff = kc * 64 + u * 8;
            *(uint4*)(smem + F1_BH + (row * PB1 + u * 8) * 2) = *(const uint4*)(g_w1h + jr * DIM + koff);
            *(uint4*)(smem + F1_BL + (row * PB1 + u * 8) * 2) = *(const uint4*)(g_w1l + jr * DIM + koff);
        }
        __syncthreads();
#pragma unroll
        for (int ks = 0; ks < 4; ks++) {
            u32 ah[4], al[4];
            ldsm4(ah, aH + kc * 128 + ks * 32);
            ldsm4(al, aL + kc * 128 + ks * 32);
#pragma unroll
            for (int jp = 0; jp < 8; jp++) {
                u32 bh[4], bl[4];
                ldsm4(bh, bH4 + jp * (16 * PB1 * 2) + ks * 32);
                ldsm4(bl, bL4 + jp * (16 * PB1 * 2) + ks * 32);
                mma16816(acc[2 * jp],     ah, &bh[0]);
                mma16816(acc[2 * jp],     ah, &bl[0]);
                mma16816(acc[2 * jp],     al, &bh[0]);
                mma16816(acc[2 * jp + 1], ah, &bh[2]);
                mma16816(acc[2 * jp + 1], ah, &bl[2]);
                mma16816(acc[2 * jp + 1], al, &bh[2]);
            }
        }
        __syncthreads();
    }

    long n0 = nbase + wid * 16 + (lane >> 2);
    long n1 = n0 + 8;
    u32* ghi = (u32*)g_hidhi;
    u32* glo = (u32*)g_hidlo;
#pragma unroll
    for (int jt = 0; jt < 16; jt++) {
        int jg = jhalf * 128 + jt * 8 + (lane & 3) * 2;
        float bj0 = __ldg(&b1[jg]), bj1 = __ldg(&b1[jg + 1]);
#pragma unroll
        for (int half = 0; half < 2; half++) {
            long n = half ? n1 : n0;
            if (n < N_NODES) {
                float a0 = acc[jt][half * 2 + 0] + bj0;
                float a1 = acc[jt][half * 2 + 1] + bj1;
                float y0 = 0.5f * a0 * (1.0f + erff(a0 * 0.7071067811865476f));
                float y1 = 0.5f * a1 * (1.0f + erff(a1 * 0.7071067811865476f));
                __nv_bfloat162 ph, pl;
                bsplit(y0, ph.x, pl.x);
                bsplit(y1, ph.y, pl.y);
                ghi[n * (HID / 2) + (jg >> 1)] = *(u32*)&ph;
                glo[n * (HID / 2) + (jg >> 1)] = *(u32*)&pl;
            }
        }
    }
}

// ---------------- FFN layer 2 (HMMA, K-chunked, 2 CTA/SM) ---------------------
// CTA: 128 nodes x 64 j (blockIdx.y = j-half of 128). K=256 in 2 chunks of 128.
#define PC 136           // chunk row stride (K=128 + pad)
#define F2_AH 0
#define F2_AL (128 * PC * 2)
#define F2_BH (2 * 128 * PC * 2)
#define F2_BL (2 * 128 * PC * 2 + 64 * PC * 2)
#define F2_SMEM (2 * 128 * PC * 2 + 2 * 64 * PC * 2)   // 104,448 B
__global__ void __launch_bounds__(256, 2) ffn2_mma(const float* __restrict__ b2,
                                                   float* __restrict__ out) {
    extern __shared__ char smem[];
    u32 sb = smem_u32(smem);
    int tid = threadIdx.x;
    int wid = tid >> 5, lane = tid & 31;
    int jq = blockIdx.y;
    long nbase = (long)blockIdx.x * 128;

    u32 a_row = (u32)(wid * 16 + (lane & 15));
    u32 a_col = (u32)((lane >> 4) * 8);
    u32 aH = sb + F2_AH + (a_row * PC + a_col) * 2;
    u32 aL = sb + F2_AL + (a_row * PC + a_col) * 2;
    int g = lane >> 3;
    u32 brow = (u32)((g >> 1) * 8 + (lane & 7));
    u32 bcol = (u32)((g & 1) * 8);
    u32 bH4 = sb + F2_BH + (brow * PC + bcol) * 2;
    u32 bL4 = sb + F2_BL + (brow * PC + bcol) * 2;

    float acc[8][4];
#pragma unroll
    for (int t = 0; t < 8; t++)
#pragma unroll
        for (int q = 0; q < 4; q++) acc[t][q] = 0.f;

#pragma unroll
    for (int kc = 0; kc < 2; kc++) {
        // stage A chunk: 128 rows x 128 k (hi/lo)
        for (int idx = tid; idx < 128 * 16; idx += 256) {
            int row = idx >> 4, u = idx & 15;
            long n = nbase + row; if (n >= N_NODES) n = N_NODES - 1;
            long koff = kc * 128 + u * 8;
            *(uint4*)(smem + F2_AH + (row * PC + u * 8) * 2) = *(const uint4*)(g_hidhi + n * HID + koff);
            *(uint4*)(smem + F2_AL + (row * PC + u * 8) * 2) = *(const uint4*)(g_hidlo + n * HID + koff);
        }
        // stage B chunk: 64 j-rows x 128 k
        for (int idx = tid; idx < 64 * 16; idx += 256) {
            int row = idx >> 4, u = idx & 15;
            long jr = (long)jq * 64 + row;
            long koff = kc * 128 + u * 8;
            *(uint4*)(smem + F2_BH + (row * PC + u * 8) * 2) = *(const uint4*)(g_w2h + jr * HID + koff);
            *(uint4*)(smem + F2_BL + (row * PC + u * 8) * 2) = *(const uint4*)(g_w2l + jr * HID + koff);
        }
        __syncthreads();
#pragma unroll
        for (int ks = 0; ks < 8; ks++) {
            u32 ah[4], al[4];
            ldsm4(ah, aH + ks * 32);
            ldsm4(al, aL + ks * 32);
#pragma unroll
            for (int jp = 0; jp < 4; jp++) {
                u32 bh[4], bl[4];
                ldsm4(bh, bH4 + jp * (16 * PC * 2) + ks * 32);
                ldsm4(bl, bL4 + jp * (16 * PC * 2) + ks * 32);
                mma16816(acc[2 * jp],     ah, &bh[0]);
                mma16816(acc[2 * jp],     ah, &bl[0]);
                mma16816(acc[2 * jp],     al, &bh[0]);
                mma16816(acc[2 * jp + 1], ah, &bh[2]);
                mma16816(acc[2 * jp + 1], ah, &bl[2]);
                mma16816(acc[2 * jp + 1], al, &bh[2]);
            }
        }
        __syncthreads();
    }

    long n0 = nbase + wid * 16 + (lane >> 2);
    long n1 = n0 + 8;
#pragma unroll
    for (int jt = 0; jt < 8; jt++) {
        int jg = jq * 64 + jt * 8 + (lane & 3) * 2;
        float bj0 = __ldg(&b2[jg]), bj1 = __ldg(&b2[jg + 1]);
        if (n0 < N_NODES) {
            float2 v = make_float2(acc[jt][0] + bj0, acc[jt][1] + bj1);
            *(float2*)(out + n0 * DIM + jg) = v;
        }
        if (n1 < N_NODES) {
            float2 v = make_float2(acc[jt][2] + bj0, acc[jt][3] + bj1);
            *(float2*)(out + n1 * DIM + jg) = v;
        }
    }
}

// ---------------- launch ----------------------------------------------------
extern "C" void kernel_launch(void* const* d_in, const int* in_sizes, int n_in,
                              void* d_out, int out_size) {
    const float* x   = (const float*)d_in[0];
    const float* rep = (const float*)d_in[1];
    const int*   src = (const int*)d_in[2];
    const int*   dst = (const int*)d_in[3];
    const float* w1  = (const float*)d_in[4];
    const float* b1  = (const float*)d_in[5];
    const float* w2  = (const float*)d_in[6];
    const float* b2  = (const float*)d_in[7];
    float* out = (float*)d_out;

    static int smem_set = 0;
    if (!smem_set) {
        cudaFuncSetAttribute(ffn1_mma, cudaFuncAttributeMaxDynamicSharedMemorySize, F1_SMEM);
        cudaFuncSetAttribute(ffn2_mma, cudaFuncAttributeMaxDynamicSharedMemorySize, F2_SMEM);
        smem_set = 1;
    }

    float *ha, *hb;
    cudaGetSymbolAddress((void**)&ha, g_ha);
    cudaGetSymbolAddress((void**)&hb, g_hb);

    // CSR build
    init_kernel<<<(N_NODES + 255) / 256, 256>>>(src);
    deg_hist_kernel<<<N_EDGES / 256, 256>>>(src, dst);
    scan_a_kernel<<<SCAN_B, 1024>>>();
    scan_c_kernel<<<SCAN_B, 1024>>>();
    fill_kernel<<<N_EDGES / 256, 256>>>(src, dst);

    // weight split
    wsplit_kernel<<<(2 * HID * DIM + 255) / 256, 256>>>(w1, w2);

    // forward rotation x -> ha
    rot_kernel<<<(N_NODES * DIM) / 256, 256>>>(x, rep, ha);

    // message passing: ha -> hb -> ha
    gather_kernel<<<(N_NODES * 32) / 256, 256>>>(ha, hb);
    gather_kernel<<<(N_NODES * 32) / 256, 256>>>(hb, ha);

    // FFN (inverse rotation fused into ffn1 A-staging)
    int tiles = (N_NODES + 127) / 128;
    dim3 g1(tiles, 2), g2(tiles, 2);
    ffn1_mma<<<g1, 256, F1_SMEM>>>(rep, b1);
    ffn2_mma<<<g2, 256, F2_SMEM>>>(b2, out);
}

// round 11
// speedup vs baseline: 4.6816x; 1.0110x over previous
#include <cuda_runtime.h>
#include <cuda_bf16.h>

#define N_NODES 100000
#define N_EDGES 1600000
#define DIM 128
#define HID 256
#define SCAN_B 98

typedef unsigned long long u64;
typedef unsigned int u32;

// ---------------- scratch (static device globals; no allocs allowed) --------
__device__ float g_deg[N_NODES];
__device__ int   g_cnt[N_NODES];
__device__ int   g_part[SCAN_B];
__device__ int   g_row[N_NODES + 1];
__device__ int   g_fill[N_NODES];
__device__ int2  g_csr[N_EDGES];
__device__ float g_ha[N_NODES * DIM];
__device__ float g_hb[N_NODES * DIM];
__device__ __nv_bfloat16 g_hidhi[(long)N_NODES * HID];
__device__ __nv_bfloat16 g_hidlo[(long)N_NODES * HID];
__device__ __nv_bfloat16 g_w1h[HID * DIM], g_w1l[HID * DIM];
__device__ __nv_bfloat16 g_w2h[DIM * HID], g_w2l[DIM * HID];
__device__ int   g_sh;

// ---------------- warp-MMA helpers ------------------------------------------
__device__ __forceinline__ u32 smem_u32(const void* p) {
    u32 a;
    asm("{ .reg .u64 t; cvta.to.shared.u64 t, %1; cvt.u32.u64 %0, t; }" : "=r"(a) : "l"(p));
    return a;
}
__device__ __forceinline__ void ldsm4(u32* r, u32 a) {
    asm volatile("ldmatrix.sync.aligned.m8n8.x4.shared.b16 {%0,%1,%2,%3}, [%4];"
                 : "=r"(r[0]), "=r"(r[1]), "=r"(r[2]), "=r"(r[3]) : "r"(a));
}
__device__ __forceinline__ void mma16816(float* c, const u32* a, const u32* b) {
    asm volatile("mma.sync.aligned.m16n8k16.row.col.f32.bf16.bf16.f32 "
                 "{%0,%1,%2,%3}, {%4,%5,%6,%7}, {%8,%9}, {%0,%1,%2,%3};"
                 : "+f"(c[0]), "+f"(c[1]), "+f"(c[2]), "+f"(c[3])
                 : "r"(a[0]), "r"(a[1]), "r"(a[2]), "r"(a[3]), "r"(b[0]), "r"(b[1]));
}
__device__ __forceinline__ void bsplit(float v, __nv_bfloat16& hi, __nv_bfloat16& lo) {
    hi = __float2bfloat16(v);
    lo = __float2bfloat16(v - __bfloat162float(hi));
}

// ---------------- init: zero deg/cnt + detect + weight split -----------------
__global__ void init_kernel(const int* __restrict__ src,
                            const float* __restrict__ w1, const float* __restrict__ w2) {
    int i = blockIdx.x * blockDim.x + threadIdx.x;
    if (i < N_NODES) { g_deg[i] = 0.f; g_cnt[i] = 0; }
    if (i == 0) g_sh = (src[1] == 0 && src[2] == 1) ? 1 : 0;
    if (i < HID * DIM) {
        bsplit(w1[i], g_w1h[i], g_w1l[i]);
        bsplit(w2[i], g_w2h[i], g_w2l[i]);
    }
}

__global__ void deg_hist_kernel(const int* __restrict__ src, const int* __restrict__ dst) {
    int e = blockIdx.x * blockDim.x + threadIdx.x;
    if (e < N_EDGES) {
        int sh = g_sh;
        atomicAdd(&g_deg[src[(long)e << sh]], 1.0f);
        atomicAdd(&g_cnt[dst[(long)e << sh]], 1);
    }
}

__global__ void scan_a_kernel() {
    __shared__ int s[1024];
    int t = threadIdx.x;
    int i = blockIdx.x * 1024 + t;
    s[t] = (i < N_NODES) ? g_cnt[i] : 0;
    __syncthreads();
    for (int off = 512; off > 0; off >>= 1) {
        if (t < off) s[t] += s[t + off];
        __syncthreads();
    }
    if (t == 0) g_part[blockIdx.x] = s[0];
}

__global__ void scan_c_kernel() {
    __shared__ int s[1024];
    __shared__ int base_s;
    int t = threadIdx.x;
    int b = blockIdx.x;
    int i = b * 1024 + t;
    int v = (i < N_NODES) ? g_cnt[i] : 0;
    s[t] = v;
    if (t == 0) {
        int base = 0;
        for (int k = 0; k < b; k++) base += g_part[k];
        base_s = base;
    }
    __syncthreads();
    for (int off = 1; off < 1024; off <<= 1) {
        int add = (t >= off) ? s[t - off] : 0;
        __syncthreads();
        s[t] += add;
        __syncthreads();
    }
    int base = base_s;
    if (i < N_NODES) {
        int excl = base + s[t] - v;
        g_row[i] = excl;
        g_fill[i] = excl;
        if (i == N_NODES - 1) g_row[N_NODES] = base + s[t];
    }
}

__global__ void fill_kernel(const int* __restrict__ src, const int* __restrict__ dst) {
    int e = blockIdx.x * blockDim.x + threadIdx.x;
    if (e < N_EDGES) {
        int sh = g_sh;
        int s = src[(long)e << sh];
        int d = dst[(long)e << sh];
        float c = rsqrtf(g_deg[s] * g_deg[d]);
        int pos = atomicAdd(&g_fill[d], 1);
        g_csr[pos] = make_int2(s, __float_as_int(c));
    }
}

// ---------------- forward rotation -------------------------------------------
__global__ void rot_kernel(const float* __restrict__ x, const float* __restrict__ rep,
                           float* __restrict__ out) {
    int i = blockIdx.x * blockDim.x + threadIdx.x;
    int n = i >> 7;
    int t = i & 127;
    int b = t >> 4, c = (t >> 2) & 3, el = t & 3;
    float4 r = *(const float4*)(rep + (((long)n * 8 + b) * 16 + c * 4));
    const float* xb = x + (long)n * DIM + b * 16 + el;
    out[i] = r.x * xb[0] + r.y * xb[4] + r.z * xb[8] + r.w * xb[12];
}

// ---------------- gather (unroll 4, front-batched loads) ----------------------
__global__ void gather_kernel(const float* __restrict__ hin, float* __restrict__ hout) {
    int gid = blockIdx.x * blockDim.x + threadIdx.x;
    int n = gid >> 5;
    int lane = gid & 31;
    int beg = g_row[n], end = g_row[n + 1];
    float4 acc = make_float4(0.f, 0.f, 0.f, 0.f);
    int e = beg;
    for (; e + 4 <= end; e += 4) {
        int2 c0 = g_csr[e],     c1 = g_csr[e + 1];
        int2 c2 = g_csr[e + 2], c3 = g_csr[e + 3];
        float4 v0 = __ldg((const float4*)(hin + (long)c0.x * DIM + lane * 4));
        float4 v1 = __ldg((const float4*)(hin + (long)c1.x * DIM + lane * 4));
        float4 v2 = __ldg((const float4*)(hin + (long)c2.x * DIM + lane * 4));
        float4 v3 = __ldg((const float4*)(hin + (long)c3.x * DIM + lane * 4));
        float f0 = __int_as_float(c0.y), f1 = __int_as_float(c1.y);
        float f2 = __int_as_float(c2.y), f3 = __int_as_float(c3.y);
        acc.x += v0.x * f0; acc.y += v0.y * f0; acc.z += v0.z * f0; acc.w += v0.w * f0;
        acc.x += v1.x * f1; acc.y += v1.y * f1; acc.z += v1.z * f1; acc.w += v1.w * f1;
        acc.x += v2.x * f2; acc.y += v2.y * f2; acc.z += v2.z * f2; acc.w += v2.w * f2;
        acc.x += v3.x * f3; acc.y += v3.y * f3; acc.z += v3.z * f3; acc.w += v3.w * f3;
    }
    for (; e < end; e++) {
        int2 c0 = g_csr[e];
        float4 v0 = __ldg((const float4*)(hin + (long)c0.x * DIM + lane * 4));
        float f0 = __int_as_float(c0.y);
        acc.x += v0.x * f0; acc.y += v0.y * f0; acc.z += v0.z * f0; acc.w += v0.w * f0;
    }
    *(float4*)(hout + (long)n * DIM + lane * 4) = acc;
}

// ---------------- FFN layer 1 (HMMA, fused inverse rotation, 2 CTA/SM) --------
#define P1  136
#define PB1 72
#define F1_AH 0
#define F1_AL (128 * P1 * 2)
#define F1_BH (2 * 128 * P1 * 2)
#define F1_BL (2 * 128 * P1 * 2 + 128 * PB1 * 2)
#define F1_SMEM (2 * 128 * P1 * 2 + 2 * 128 * PB1 * 2)   // 106,496 B
__global__ void __launch_bounds__(256, 2) ffn1_mma(const float* __restrict__ rep,
                                                   const float* __restrict__ b1) {
    extern __shared__ char smem[];
    u32 sb = smem_u32(smem);
    int tid = threadIdx.x;
    int wid = tid >> 5, lane = tid & 31;
    int jhalf = blockIdx.y;
    long nbase = (long)blockIdx.x * 128;

    // stage A: rot_t(g_ha) split to hi/lo (full K)
    for (int idx = tid; idx < 128 * 16; idx += 256) {
        int row = idx >> 4, u = idx & 15;
        long n = nbase + row; if (n >= N_NODES) n = N_NODES - 1;
        int b = u >> 1;
        const float4* hv = (const float4*)(g_ha + n * DIM + b * 16);
        float4 q0 = hv[0], q1 = hv[1], q2 = hv[2], q3 = hv[3];
        const float4* rv = (const float4*)(rep + ((long)n * 8 + b) * 16);
        float4 R0 = rv[0], R1 = rv[1], R2 = rv[2], R3 = rv[3];
        float rc[2][4];
        if (u & 1) {
            rc[0][0] = R0.z; rc[0][1] = R1.z; rc[0][2] = R2.z; rc[0][3] = R3.z;
            rc[1][0] = R0.w; rc[1][1] = R1.w; rc[1][2] = R2.w; rc[1][3] = R3.w;
        } else {
            rc[0][0] = R0.x; rc[0][1] = R1.x; rc[0][2] = R2.x; rc[0][3] = R3.x;
            rc[1][0] = R0.y; rc[1][1] = R1.y; rc[1][2] = R2.y; rc[1][3] = R3.y;
        }
        __nv_bfloat16 hi[8], lo[8];
#pragma unroll
        for (int cc = 0; cc < 2; cc++) {
            float v0 = rc[cc][0] * q0.x + rc[cc][1] * q1.x + rc[cc][2] * q2.x + rc[cc][3] * q3.x;
            float v1 = rc[cc][0] * q0.y + rc[cc][1] * q1.y + rc[cc][2] * q2.y + rc[cc][3] * q3.y;
            float v2 = rc[cc][0] * q0.z + rc[cc][1] * q1.z + rc[cc][2] * q2.z + rc[cc][3] * q3.z;
            float v3 = rc[cc][0] * q0.w + rc[cc][1] * q1.w + rc[cc][2] * q2.w + rc[cc][3] * q3.w;
            bsplit(v0, hi[cc * 4 + 0], lo[cc * 4 + 0]);
            bsplit(v1, hi[cc * 4 + 1], lo[cc * 4 + 1]);
            bsplit(v2, hi[cc * 4 + 2], lo[cc * 4 + 2]);
            bsplit(v3, hi[cc * 4 + 3], lo[cc * 4 + 3]);
        }
        *(uint4*)(smem + F1_AH + (row * P1 + u * 8) * 2) = *(uint4*)hi;
        *(uint4*)(smem + F1_AL + (row * P1 + u * 8) * 2) = *(uint4*)lo;
    }

    u32 a_row = (u32)(wid * 16 + (lane & 15));
    u32 a_col = (u32)((lane >> 4) * 8);
    u32 aH = sb + F1_AH + (a_row * P1 + a_col) * 2;
    u32 aL = sb + F1_AL + (a_row * P1 + a_col) * 2;
    int g = lane >> 3;
    u32 brow = (u32)((g >> 1) * 8 + (lane & 7));
    u32 bcol = (u32)((g & 1) * 8);
    u32 bH4 = sb + F1_BH + (brow * PB1 + bcol) * 2;
    u32 bL4 = sb + F1_BL + (brow * PB1 + bcol) * 2;

    float acc[16][4];
#pragma unroll
    for (int t = 0; t < 16; t++)
#pragma unroll
        for (int q = 0; q < 4; q++) acc[t][q] = 0.f;

#pragma unroll
    for (int kc = 0; kc < 2; kc++) {
        for (int idx = tid; idx < 128 * 8; idx += 256) {
            int row = idx >> 3, u = idx & 7;
            long jr = (long)jhalf * 128 + row;
            long koff = kc * 64 + u * 8;
            *(uint4*)(smem + F1_BH + (row * PB1 + u * 8) * 2) = *(const uint4*)(g_w1h + jr * DIM + koff);
            *(uint4*)(smem + F1_BL + (row * PB1 + u * 8) * 2) = *(const uint4*)(g_w1l + jr * DIM + koff);
        }
        __syncthreads();
#pragma unroll
        for (int ks = 0; ks < 4; ks++) {
            u32 ah[4], al[4];
            ldsm4(ah, aH + kc * 128 + ks * 32);
            ldsm4(al, aL + kc * 128 + ks * 32);
#pragma unroll
            for (int jp = 0; jp < 8; jp++) {
                u32 bh[4], bl[4];
                ldsm4(bh, bH4 + jp * (16 * PB1 * 2) + ks * 32);
                ldsm4(bl, bL4 + jp * (16 * PB1 * 2) + ks * 32);
                mma16816(acc[2 * jp],     ah, &bh[0]);
                mma16816(acc[2 * jp],     ah, &bl[0]);
                mma16816(acc[2 * jp],     al, &bh[0]);
                mma16816(acc[2 * jp + 1], ah, &bh[2]);
                mma16816(acc[2 * jp + 1], ah, &bl[2]);
                mma16816(acc[2 * jp + 1], al, &bh[2]);
            }
        }
        __syncthreads();
    }

    long n0 = nbase + wid * 16 + (lane >> 2);
    long n1 = n0 + 8;
    u32* ghi = (u32*)g_hidhi;
    u32* glo = (u32*)g_hidlo;
#pragma unroll
    for (int jt = 0; jt < 16; jt++) {
        int jg = jhalf * 128 + jt * 8 + (lane & 3) * 2;
        float bj0 = __ldg(&b1[jg]), bj1 = __ldg(&b1[jg + 1]);
#pragma unroll
        for (int half = 0; half < 2; half++) {
            long n = half ? n1 : n0;
            if (n < N_NODES) {
                float a0 = acc[jt][half * 2 + 0] + bj0;
                float a1 = acc[jt][half * 2 + 1] + bj1;
                float y0 = 0.5f * a0 * (1.0f + erff(a0 * 0.7071067811865476f));
                float y1 = 0.5f * a1 * (1.0f + erff(a1 * 0.7071067811865476f));
                __nv_bfloat162 ph, pl;
                bsplit(y0, ph.x, pl.x);
                bsplit(y1, ph.y, pl.y);
                ghi[n * (HID / 2) + (jg >> 1)] = *(u32*)&ph;
                glo[n * (HID / 2) + (jg >> 1)] = *(u32*)&pl;
            }
        }
    }
}

// ---------------- FFN layer 2 (HMMA, 4 K-chunks of 64, 3 CTA/SM) --------------
#define PC2 72
#define F2_AH 0
#define F2_AL (128 * PC2 * 2)
#define F2_BH (2 * 128 * PC2 * 2)
#define F2_BL (2 * 128 * PC2 * 2 + 64 * PC2 * 2)
#define F2_SMEM (2 * 128 * PC2 * 2 + 2 * 64 * PC2 * 2)   // 55,296 B
__global__ void __launch_bounds__(256, 3) ffn2_mma(const float* __restrict__ b2,
                                                   float* __restrict__ out) {
    extern __shared__ char smem[];
    u32 sb = smem_u32(smem);
    int tid = threadIdx.x;
    int wid = tid >> 5, lane = tid & 31;
    int jq = blockIdx.y;
    long nbase = (long)blockIdx.x * 128;

    u32 a_row = (u32)(wid * 16 + (lane & 15));
    u32 a_col = (u32)((lane >> 4) * 8);
    u32 aH = sb + F2_AH + (a_row * PC2 + a_col) * 2;
    u32 aL = sb + F2_AL + (a_row * PC2 + a_col) * 2;
    int g = lane >> 3;
    u32 brow = (u32)((g >> 1) * 8 + (lane & 7));
    u32 bcol = (u32)((g & 1) * 8);
    u32 bH4 = sb + F2_BH + (brow * PC2 + bcol) * 2;
    u32 bL4 = sb + F2_BL + (brow * PC2 + bcol) * 2;

    float acc[8][4];
#pragma unroll
    for (int t = 0; t < 8; t++)
#pragma unroll
        for (int q = 0; q < 4; q++) acc[t][q] = 0.f;

#pragma unroll
    for (int kc = 0; kc < 4; kc++) {
        // stage A chunk: 128 rows x 64 k (hi/lo)
        for (int idx = tid; idx < 128 * 8; idx += 256) {
            int row = idx >> 3, u = idx & 7;
            long n = nbase + row; if (n >= N_NODES) n = N_NODES - 1;
            long koff = kc * 64 + u * 8;
            *(uint4*)(smem + F2_AH + (row * PC2 + u * 8) * 2) = *(const uint4*)(g_hidhi + n * HID + koff);
            *(uint4*)(smem + F2_AL + (row * PC2 + u * 8) * 2) = *(const uint4*)(g_hidlo + n * HID + koff);
        }
        // stage B chunk: 64 j-rows x 64 k
        for (int idx = tid; idx < 64 * 8; idx += 256) {
            int row = idx >> 3, u = idx & 7;
            long jr = (long)jq * 64 + row;
            long koff = kc * 64 + u * 8;
            *(uint4*)(smem + F2_BH + (row * PC2 + u * 8) * 2) = *(const uint4*)(g_w2h + jr * HID + koff);
            *(uint4*)(smem + F2_BL + (row * PC2 + u * 8) * 2) = *(const uint4*)(g_w2l + jr * HID + koff);
        }
        __syncthreads();
#pragma unroll
        for (int ks = 0; ks < 4; ks++) {
            u32 ah[4], al[4];
            ldsm4(ah, aH + ks * 32);
            ldsm4(al, aL + ks * 32);
#pragma unroll
            for (int jp = 0; jp < 4; jp++) {
                u32 bh[4], bl[4];
                ldsm4(bh, bH4 + jp * (16 * PC2 * 2) + ks * 32);
                ldsm4(bl, bL4 + jp * (16 * PC2 * 2) + ks * 32);
                mma16816(acc[2 * jp],     ah, &bh[0]);
                mma16816(acc[2 * jp],     ah, &bl[0]);
                mma16816(acc[2 * jp],     al, &bh[0]);
                mma16816(acc[2 * jp + 1], ah, &bh[2]);
                mma16816(acc[2 * jp + 1], ah, &bl[2]);
                mma16816(acc[2 * jp + 1], al, &bh[2]);
            }
        }
        __syncthreads();
    }

    long n0 = nbase + wid * 16 + (lane >> 2);
    long n1 = n0 + 8;
#pragma unroll
    for (int jt = 0; jt < 8; jt++) {
        int jg = jq * 64 + jt * 8 + (lane & 3) * 2;
        float bj0 = __ldg(&b2[jg]), bj1 = __ldg(&b2[jg + 1]);
        if (n0 < N_NODES) {
            float2 v = make_float2(acc[jt][0] + bj0, acc[jt][1] + bj1);
            *(float2*)(out + n0 * DIM + jg) = v;
        }
        if (n1 < N_NODES) {
            float2 v = make_float2(acc[jt][2] + bj0, acc[jt][3] + bj1);
            *(float2*)(out + n1 * DIM + jg) = v;
        }
    }
}

// ---------------- launch ----------------------------------------------------
extern "C" void kernel_launch(void* const* d_in, const int* in_sizes, int n_in,
                              void* d_out, int out_size) {
    const float* x   = (const float*)d_in[0];
    const float* rep = (const float*)d_in[1];
    const int*   src = (const int*)d_in[2];
    const int*   dst = (const int*)d_in[3];
    const float* w1  = (const float*)d_in[4];
    const float* b1  = (const float*)d_in[5];
    const float* w2  = (const float*)d_in[6];
    const float* b2  = (const float*)d_in[7];
    float* out = (float*)d_out;

    static int smem_set = 0;
    if (!smem_set) {
        cudaFuncSetAttribute(ffn1_mma, cudaFuncAttributeMaxDynamicSharedMemorySize, F1_SMEM);
        cudaFuncSetAttribute(ffn2_mma, cudaFuncAttributeMaxDynamicSharedMemorySize, F2_SMEM);
        smem_set = 1;
    }

    float *ha, *hb;
    cudaGetSymbolAddress((void**)&ha, g_ha);
    cudaGetSymbolAddress((void**)&hb, g_hb);

    // CSR build (+ weight split fused into init)
    init_kernel<<<(N_NODES + 255) / 256, 256>>>(src, w1, w2);
    deg_hist_kernel<<<N_EDGES / 256, 256>>>(src, dst);
    scan_a_kernel<<<SCAN_B, 1024>>>();
    scan_c_kernel<<<SCAN_B, 1024>>>();
    fill_kernel<<<N_EDGES / 256, 256>>>(src, dst);

    // forward rotation x -> ha
    rot_kernel<<<(N_NODES * DIM) / 256, 256>>>(x, rep, ha);

    // message passing: ha -> hb -> ha
    gather_kernel<<<(N_NODES * 32) / 256, 256>>>(ha, hb);
    gather_kernel<<<(N_NODES * 32) / 256, 256>>>(hb, ha);

    // FFN (inverse rotation fused into ffn1 A-staging)
    int tiles = (N_NODES + 127) / 128;
    dim3 g1(tiles, 2), g2(tiles, 2);
    ffn1_mma<<<g1, 256, F1_SMEM>>>(rep, b1);
    ffn2_mma<<<g2, 256, F2_SMEM>>>(b2, out);
}

// round 12
// speedup vs baseline: 4.8863x; 1.0437x over previous
#include <cuda_runtime.h>
#include <cuda_bf16.h>

#define N_NODES 100000
#define N_EDGES 1600000
#define DIM 128
#define HID 256
#define SCAN_B 98

typedef unsigned long long u64;
typedef unsigned int u32;

// ---------------- scratch (static device globals; no allocs allowed) --------
__device__ float g_deg[N_NODES];
__device__ int   g_cnt[N_NODES];
__device__ int   g_part[SCAN_B];
__device__ int   g_row[N_NODES + 1];
__device__ int   g_fill[N_NODES];
__device__ int2  g_csr[N_EDGES];
__device__ float g_ha[N_NODES * DIM];
__device__ float g_hb[N_NODES * DIM];
__device__ __nv_bfloat16 g_hidhi[(long)N_NODES * HID];
__device__ __nv_bfloat16 g_hidlo[(long)N_NODES * HID];
__device__ __nv_bfloat16 g_w1h[HID * DIM], g_w1l[HID * DIM];
__device__ __nv_bfloat16 g_w2h[DIM * HID], g_w2l[DIM * HID];
__device__ int   g_sh;

// ---------------- warp-MMA helpers ------------------------------------------
__device__ __forceinline__ u32 smem_u32(const void* p) {
    u32 a;
    asm("{ .reg .u64 t; cvta.to.shared.u64 t, %1; cvt.u32.u64 %0, t; }" : "=r"(a) : "l"(p));
    return a;
}
__device__ __forceinline__ void ldsm4(u32* r, u32 a) {
    asm volatile("ldmatrix.sync.aligned.m8n8.x4.shared.b16 {%0,%1,%2,%3}, [%4];"
                 : "=r"(r[0]), "=r"(r[1]), "=r"(r[2]), "=r"(r[3]) : "r"(a));
}
__device__ __forceinline__ void mma16816(float* c, const u32* a, const u32* b) {
    asm volatile("mma.sync.aligned.m16n8k16.row.col.f32.bf16.bf16.f32 "
                 "{%0,%1,%2,%3}, {%4,%5,%6,%7}, {%8,%9}, {%0,%1,%2,%3};"
                 : "+f"(c[0]), "+f"(c[1]), "+f"(c[2]), "+f"(c[3])
                 : "r"(a[0]), "r"(a[1]), "r"(a[2]), "r"(a[3]), "r"(b[0]), "r"(b[1]));
}
__device__ __forceinline__ void bsplit(float v, __nv_bfloat16& hi, __nv_bfloat16& lo) {
    hi = __float2bfloat16(v);
    lo = __float2bfloat16(v - __bfloat162float(hi));
}

// ---------------- init: zero deg/cnt + detect + weight split -----------------
__global__ void init_kernel(const int* __restrict__ src,
                            const float* __restrict__ w1, const float* __restrict__ w2) {
    int i = blockIdx.x * blockDim.x + threadIdx.x;
    if (i < N_NODES) { g_deg[i] = 0.f; g_cnt[i] = 0; }
    if (i == 0) g_sh = (src[1] == 0 && src[2] == 1) ? 1 : 0;
    if (i < HID * DIM) {
        bsplit(w1[i], g_w1h[i], g_w1l[i]);
        bsplit(w2[i], g_w2h[i], g_w2l[i]);
    }
}

__global__ void deg_hist_kernel(const int* __restrict__ src, const int* __restrict__ dst) {
    int e = blockIdx.x * blockDim.x + threadIdx.x;
    if (e < N_EDGES) {
        int sh = g_sh;
        atomicAdd(&g_deg[src[(long)e << sh]], 1.0f);
        atomicAdd(&g_cnt[dst[(long)e << sh]], 1);
    }
}

__global__ void scan_a_kernel() {
    __shared__ int s[1024];
    int t = threadIdx.x;
    int i = blockIdx.x * 1024 + t;
    s[t] = (i < N_NODES) ? g_cnt[i] : 0;
    __syncthreads();
    for (int off = 512; off > 0; off >>= 1) {
        if (t < off) s[t] += s[t + off];
        __syncthreads();
    }
    if (t == 0) g_part[blockIdx.x] = s[0];
}

__global__ void scan_c_kernel() {
    __shared__ int s[1024];
    __shared__ int base_s;
    int t = threadIdx.x;
    int b = blockIdx.x;
    int i = b * 1024 + t;
    int v = (i < N_NODES) ? g_cnt[i] : 0;
    s[t] = v;
    if (t == 0) {
        int base = 0;
        for (int k = 0; k < b; k++) base += g_part[k];
        base_s = base;
    }
    __syncthreads();
    for (int off = 1; off < 1024; off <<= 1) {
        int add = (t >= off) ? s[t - off] : 0;
        __syncthreads();
        s[t] += add;
        __syncthreads();
    }
    int base = base_s;
    if (i < N_NODES) {
        int excl = base + s[t] - v;
        g_row[i] = excl;
        g_fill[i] = excl;
        if (i == N_NODES - 1) g_row[N_NODES] = base + s[t];
    }
}

__global__ void fill_kernel(const int* __restrict__ src, const int* __restrict__ dst) {
    int e = blockIdx.x * blockDim.x + threadIdx.x;
    if (e < N_EDGES) {
        int sh = g_sh;
        int s = src[(long)e << sh];
        int d = dst[(long)e << sh];
        float c = rsqrtf(g_deg[s] * g_deg[d]);
        int pos = atomicAdd(&g_fill[d], 1);
        g_csr[pos] = make_int2(s, __float_as_int(c));
    }
}

// ---------------- forward rotation -------------------------------------------
__global__ void rot_kernel(const float* __restrict__ x, const float* __restrict__ rep,
                           float* __restrict__ out) {
    int i = blockIdx.x * blockDim.x + threadIdx.x;
    int n = i >> 7;
    int t = i & 127;
    int b = t >> 4, c = (t >> 2) & 3, el = t & 3;
    float4 r = *(const float4*)(rep + (((long)n * 8 + b) * 16 + c * 4));
    const float* xb = x + (long)n * DIM + b * 16 + el;
    out[i] = r.x * xb[0] + r.y * xb[4] + r.z * xb[8] + r.w * xb[12];
}

// ---------------- gather (unroll 4, front-batched loads) ----------------------
__global__ void gather_kernel(const float* __restrict__ hin, float* __restrict__ hout) {
    int gid = blockIdx.x * blockDim.x + threadIdx.x;
    int n = gid >> 5;
    int lane = gid & 31;
    int beg = g_row[n], end = g_row[n + 1];
    float4 acc = make_float4(0.f, 0.f, 0.f, 0.f);
    int e = beg;
    for (; e + 4 <= end; e += 4) {
        int2 c0 = g_csr[e],     c1 = g_csr[e + 1];
        int2 c2 = g_csr[e + 2], c3 = g_csr[e + 3];
        float4 v0 = __ldg((const float4*)(hin + (long)c0.x * DIM + lane * 4));
        float4 v1 = __ldg((const float4*)(hin + (long)c1.x * DIM + lane * 4));
        float4 v2 = __ldg((const float4*)(hin + (long)c2.x * DIM + lane * 4));
        float4 v3 = __ldg((const float4*)(hin + (long)c3.x * DIM + lane * 4));
        float f0 = __int_as_float(c0.y), f1 = __int_as_float(c1.y);
        float f2 = __int_as_float(c2.y), f3 = __int_as_float(c3.y);
        acc.x += v0.x * f0; acc.y += v0.y * f0; acc.z += v0.z * f0; acc.w += v0.w * f0;
        acc.x += v1.x * f1; acc.y += v1.y * f1; acc.z += v1.z * f1; acc.w += v1.w * f1;
        acc.x += v2.x * f2; acc.y += v2.y * f2; acc.z += v2.z * f2; acc.w += v2.w * f2;
        acc.x += v3.x * f3; acc.y += v3.y * f3; acc.z += v3.z * f3; acc.w += v3.w * f3;
    }
    for (; e < end; e++) {
        int2 c0 = g_csr[e];
        float4 v0 = __ldg((const float4*)(hin + (long)c0.x * DIM + lane * 4));
        float f0 = __int_as_float(c0.y);
        acc.x += v0.x * f0; acc.y += v0.y * f0; acc.z += v0.z * f0; acc.w += v0.w * f0;
    }
    *(float4*)(hout + (long)n * DIM + lane * 4) = acc;
}

// ---------------- FFN layer 1 (HMMA, fused rot_t, single-pass A) --------------
// CTA: 64 nodes x ALL 256 j. Warp = 16 nodes x 128 j (jh = wid>>2, group = wid&3).
// A (full K=128, hi/lo) resident; B staged in two K=64 chunks.
#define P1  136
#define PB1 72
#define F1_AH 0
#define F1_AL (64 * P1 * 2)
#define F1_BH (2 * 64 * P1 * 2)
#define F1_BL (2 * 64 * P1 * 2 + 256 * PB1 * 2)
#define F1_SMEM (2 * 64 * P1 * 2 + 2 * 256 * PB1 * 2)   // 108,544 B
__global__ void __launch_bounds__(256, 2) ffn1_mma(const float* __restrict__ rep,
                                                   const float* __restrict__ b1) {
    extern __shared__ char smem[];
    u32 sb = smem_u32(smem);
    int tid = threadIdx.x;
    int wid = tid >> 5, lane = tid & 31;
    int wg = wid & 3, jh = wid >> 2;
    long nbase = (long)blockIdx.x * 64;

    // stage A: rot_t(g_ha) split to hi/lo (64 rows, full K) — done ONCE
    for (int idx = tid; idx < 64 * 16; idx += 256) {
        int row = idx >> 4, u = idx & 15;
        long n = nbase + row; if (n >= N_NODES) n = N_NODES - 1;
        int b = u >> 1;
        const float4* hv = (const float4*)(g_ha + n * DIM + b * 16);
        float4 q0 = hv[0], q1 = hv[1], q2 = hv[2], q3 = hv[3];
        const float4* rv = (const float4*)(rep + ((long)n * 8 + b) * 16);
        float4 R0 = rv[0], R1 = rv[1], R2 = rv[2], R3 = rv[3];
        float rc[2][4];
        if (u & 1) {
            rc[0][0] = R0.z; rc[0][1] = R1.z; rc[0][2] = R2.z; rc[0][3] = R3.z;
            rc[1][0] = R0.w; rc[1][1] = R1.w; rc[1][2] = R2.w; rc[1][3] = R3.w;
        } else {
            rc[0][0] = R0.x; rc[0][1] = R1.x; rc[0][2] = R2.x; rc[0][3] = R3.x;
            rc[1][0] = R0.y; rc[1][1] = R1.y; rc[1][2] = R2.y; rc[1][3] = R3.y;
        }
        __nv_bfloat16 hi[8], lo[8];
#pragma unroll
        for (int cc = 0; cc < 2; cc++) {
            float v0 = rc[cc][0] * q0.x + rc[cc][1] * q1.x + rc[cc][2] * q2.x + rc[cc][3] * q3.x;
            float v1 = rc[cc][0] * q0.y + rc[cc][1] * q1.y + rc[cc][2] * q2.y + rc[cc][3] * q3.y;
            float v2 = rc[cc][0] * q0.z + rc[cc][1] * q1.z + rc[cc][2] * q2.z + rc[cc][3] * q3.z;
            float v3 = rc[cc][0] * q0.w + rc[cc][1] * q1.w + rc[cc][2] * q2.w + rc[cc][3] * q3.w;
            bsplit(v0, hi[cc * 4 + 0], lo[cc * 4 + 0]);
            bsplit(v1, hi[cc * 4 + 1], lo[cc * 4 + 1]);
            bsplit(v2, hi[cc * 4 + 2], lo[cc * 4 + 2]);
            bsplit(v3, hi[cc * 4 + 3], lo[cc * 4 + 3]);
        }
        *(uint4*)(smem + F1_AH + (row * P1 + u * 8) * 2) = *(uint4*)hi;
        *(uint4*)(smem + F1_AL + (row * P1 + u * 8) * 2) = *(uint4*)lo;
    }

    u32 a_row = (u32)(wg * 16 + (lane & 15));
    u32 a_col = (u32)((lane >> 4) * 8);
    u32 aH = sb + F1_AH + (a_row * P1 + a_col) * 2;
    u32 aL = sb + F1_AL + (a_row * P1 + a_col) * 2;
    int g = lane >> 3;
    u32 brow = (u32)(jh * 128 + (g >> 1) * 8 + (lane & 7));
    u32 bcol = (u32)((g & 1) * 8);
    u32 bH4 = sb + F1_BH + (brow * PB1 + bcol) * 2;
    u32 bL4 = sb + F1_BL + (brow * PB1 + bcol) * 2;

    float acc[16][4];
#pragma unroll
    for (int t = 0; t < 16; t++)
#pragma unroll
        for (int q = 0; q < 4; q++) acc[t][q] = 0.f;

#pragma unroll
    for (int kc = 0; kc < 2; kc++) {
        // stage B chunk: 256 j-rows x 64 k
        for (int idx = tid; idx < 256 * 8; idx += 256) {
            int row = idx >> 3, u = idx & 7;
            long koff = kc * 64 + u * 8;
            *(uint4*)(smem + F1_BH + (row * PB1 + u * 8) * 2) = *(const uint4*)(g_w1h + (long)row * DIM + koff);
            *(uint4*)(smem + F1_BL + (row * PB1 + u * 8) * 2) = *(const uint4*)(g_w1l + (long)row * DIM + koff);
        }
        __syncthreads();
#pragma unroll
        for (int ks = 0; ks < 4; ks++) {
            u32 ah[4], al[4];
            ldsm4(ah, aH + kc * 128 + ks * 32);
            ldsm4(al, aL + kc * 128 + ks * 32);
#pragma unroll
            for (int jp = 0; jp < 8; jp++) {
                u32 bh[4], bl[4];
                ldsm4(bh, bH4 + jp * (16 * PB1 * 2) + ks * 32);
                ldsm4(bl, bL4 + jp * (16 * PB1 * 2) + ks * 32);
                mma16816(acc[2 * jp],     ah, &bh[0]);
                mma16816(acc[2 * jp],     ah, &bl[0]);
                mma16816(acc[2 * jp],     al, &bh[0]);
                mma16816(acc[2 * jp + 1], ah, &bh[2]);
                mma16816(acc[2 * jp + 1], ah, &bl[2]);
                mma16816(acc[2 * jp + 1], al, &bh[2]);
            }
        }
        __syncthreads();
    }

    long n0 = nbase + wg * 16 + (lane >> 2);
    long n1 = n0 + 8;
    u32* ghi = (u32*)g_hidhi;
    u32* glo = (u32*)g_hidlo;
#pragma unroll
    for (int jt = 0; jt < 16; jt++) {
        int jg = jh * 128 + jt * 8 + (lane & 3) * 2;
        float bj0 = __ldg(&b1[jg]), bj1 = __ldg(&b1[jg + 1]);
#pragma unroll
        for (int half = 0; half < 2; half++) {
            long n = half ? n1 : n0;
            if (n < N_NODES) {
                float a0 = acc[jt][half * 2 + 0] + bj0;
                float a1 = acc[jt][half * 2 + 1] + bj1;
                float y0 = 0.5f * a0 * (1.0f + erff(a0 * 0.7071067811865476f));
                float y1 = 0.5f * a1 * (1.0f + erff(a1 * 0.7071067811865476f));
                __nv_bfloat162 ph, pl;
                bsplit(y0, ph.x, pl.x);
                bsplit(y1, ph.y, pl.y);
                ghi[n * (HID / 2) + (jg >> 1)] = *(u32*)&ph;
                glo[n * (HID / 2) + (jg >> 1)] = *(u32*)&pl;
            }
        }
    }
}

// ---------------- FFN layer 2 (HMMA, all-j CTA, 4 K-chunks) -------------------
// CTA: 128 nodes x ALL 128 j. Warp = 16 nodes x 128 j. hid read ONCE.
#define PC2 72
#define F2_AH 0
#define F2_AL (128 * PC2 * 2)
#define F2_BH (2 * 128 * PC2 * 2)
#define F2_BL (2 * 128 * PC2 * 2 + 128 * PC2 * 2)
#define F2_SMEM (4 * 128 * PC2 * 2)                     // 73,728 B
__global__ void __launch_bounds__(256, 2) ffn2_mma(const float* __restrict__ b2,
                                                   float* __restrict__ out) {
    extern __shared__ char smem[];
    u32 sb = smem_u32(smem);
    int tid = threadIdx.x;
    int wid = tid >> 5, lane = tid & 31;
    long nbase = (long)blockIdx.x * 128;

    u32 a_row = (u32)(wid * 16 + (lane & 15));
    u32 a_col = (u32)((lane >> 4) * 8);
    u32 aH = sb + F2_AH + (a_row * PC2 + a_col) * 2;
    u32 aL = sb + F2_AL + (a_row * PC2 + a_col) * 2;
    int g = lane >> 3;
    u32 brow = (u32)((g >> 1) * 8 + (lane & 7));
    u32 bcol = (u32)((g & 1) * 8);
    u32 bH4 = sb + F2_BH + (brow * PC2 + bcol) * 2;
    u32 bL4 = sb + F2_BL + (brow * PC2 + bcol) * 2;

    float acc[16][4];
#pragma unroll
    for (int t = 0; t < 16; t++)
#pragma unroll
        for (int q = 0; q < 4; q++) acc[t][q] = 0.f;

#pragma unroll
    for (int kc = 0; kc < 4; kc++) {
        // stage A chunk: 128 rows x 64 k (hi/lo)
        for (int idx = tid; idx < 128 * 8; idx += 256) {
            int row = idx >> 3, u = idx & 7;
            long n = nbase + row; if (n >= N_NODES) n = N_NODES - 1;
            long koff = kc * 64 + u * 8;
            *(uint4*)(smem + F2_AH + (row * PC2 + u * 8) * 2) = *(const uint4*)(g_hidhi + n * HID + koff);
            *(uint4*)(smem + F2_AL + (row * PC2 + u * 8) * 2) = *(const uint4*)(g_hidlo + n * HID + koff);
        }
        // stage B chunk: 128 j-rows x 64 k
        for (int idx = tid; idx < 128 * 8; idx += 256) {
            int row = idx >> 3, u = idx & 7;
            long koff = kc * 64 + u * 8;
            *(uint4*)(smem + F2_BH + (row * PC2 + u * 8) * 2) = *(const uint4*)(g_w2h + (long)row * HID + koff);
            *(uint4*)(smem + F2_BL + (row * PC2 + u * 8) * 2) = *(const uint4*)(g_w2l + (long)row * HID + koff);
        }
        __syncthreads();
#pragma unroll
        for (int ks = 0; ks < 4; ks++) {
            u32 ah[4], al[4];
            ldsm4(ah, aH + ks * 32);
            ldsm4(al, aL + ks * 32);
#pragma unroll
            for (int jp = 0; jp < 8; jp++) {
                u32 bh[4], bl[4];
                ldsm4(bh, bH4 + jp * (16 * PC2 * 2) + ks * 32);
                ldsm4(bl, bL4 + jp * (16 * PC2 * 2) + ks * 32);
                mma16816(acc[2 * jp],     ah, &bh[0]);
                mma16816(acc[2 * jp],     ah, &bl[0]);
                mma16816(acc[2 * jp],     al, &bh[0]);
                mma16816(acc[2 * jp + 1], ah, &bh[2]);
                mma16816(acc[2 * jp + 1], ah, &bl[2]);
                mma16816(acc[2 * jp + 1], al, &bh[2]);
            }
        }
        __syncthreads();
    }

    long n0 = nbase + wid * 16 + (lane >> 2);
    long n1 = n0 + 8;
#pragma unroll
    for (int jt = 0; jt < 16; jt++) {
        int jg = jt * 8 + (lane & 3) * 2;
        float bj0 = __ldg(&b2[jg]), bj1 = __ldg(&b2[jg + 1]);
        if (n0 < N_NODES) {
            float2 v = make_float2(acc[jt][0] + bj0, acc[jt][1] + bj1);
            *(float2*)(out + n0 * DIM + jg) = v;
        }
        if (n1 < N_NODES) {
            float2 v = make_float2(acc[jt][2] + bj0, acc[jt][3] + bj1);
            *(float2*)(out + n1 * DIM + jg) = v;
        }
    }
}

// ---------------- launch ----------------------------------------------------
extern "C" void kernel_launch(void* const* d_in, const int* in_sizes, int n_in,
                              void* d_out, int out_size) {
    const float* x   = (const float*)d_in[0];
    const float* rep = (const float*)d_in[1];
    const int*   src = (const int*)d_in[2];
    const int*   dst = (const int*)d_in[3];
    const float* w1  = (const float*)d_in[4];
    const float* b1  = (const float*)d_in[5];
    const float* w2  = (const float*)d_in[6];
    const float* b2  = (const float*)d_in[7];
    float* out = (float*)d_out;

    static int smem_set = 0;
    if (!smem_set) {
        cudaFuncSetAttribute(ffn1_mma, cudaFuncAttributeMaxDynamicSharedMemorySize, F1_SMEM);
        cudaFuncSetAttribute(ffn2_mma, cudaFuncAttributeMaxDynamicSharedMemorySize, F2_SMEM);
        smem_set = 1;
    }

    float *ha, *hb;
    cudaGetSymbolAddress((void**)&ha, g_ha);
    cudaGetSymbolAddress((void**)&hb, g_hb);

    // CSR build (+ weight split fused into init)
    init_kernel<<<(N_NODES + 255) / 256, 256>>>(src, w1, w2);
    deg_hist_kernel<<<N_EDGES / 256, 256>>>(src, dst);
    scan_a_kernel<<<SCAN_B, 1024>>>();
    scan_c_kernel<<<SCAN_B, 1024>>>();
    fill_kernel<<<N_EDGES / 256, 256>>>(src, dst);

    // forward rotation x -> ha
    rot_kernel<<<(N_NODES * DIM) / 256, 256>>>(x, rep, ha);

    // message passing: ha -> hb -> ha
    gather_kernel<<<(N_NODES * 32) / 256, 256>>>(ha, hb);
    gather_kernel<<<(N_NODES * 32) / 256, 256>>>(hb, ha);

    // FFN (inverse rotation fused into ffn1 A-staging; single-pass A reads)
    ffn1_mma<<<(N_NODES + 63) / 64, 256, F1_SMEM>>>(rep, b1);
    ffn2_mma<<<(N_NODES + 127) / 128, 256, F2_SMEM>>>(b2, out);
}

// round 13
// speedup vs baseline: 5.2108x; 1.0664x over previous
#include <cuda_runtime.h>
#include <cuda_bf16.h>

#define N_NODES 100000
#define N_EDGES 1600000
#define DIM 128
#define HID 256
#define SCAN_B 98

typedef unsigned long long u64;
typedef unsigned int u32;

// ---------------- scratch (static device globals; no allocs allowed) --------
__device__ float g_deg[N_NODES];
__device__ int   g_cnt[N_NODES];
__device__ int   g_part[SCAN_B];
__device__ int   g_row[N_NODES + 1];
__device__ int   g_fill[N_NODES];
__device__ int2  g_csr[N_EDGES];
__device__ float g_ha[N_NODES * DIM];
__device__ float g_hb[N_NODES * DIM];
__device__ __nv_bfloat16 g_w1h[HID * DIM], g_w1l[HID * DIM];
__device__ __nv_bfloat16 g_w2h[DIM * HID], g_w2l[DIM * HID];
__device__ int   g_sh;

// ---------------- warp-MMA helpers ------------------------------------------
__device__ __forceinline__ u32 smem_u32(const void* p) {
    u32 a;
    asm("{ .reg .u64 t; cvta.to.shared.u64 t, %1; cvt.u32.u64 %0, t; }" : "=r"(a) : "l"(p));
    return a;
}
__device__ __forceinline__ void ldsm4(u32* r, u32 a) {
    asm volatile("ldmatrix.sync.aligned.m8n8.x4.shared.b16 {%0,%1,%2,%3}, [%4];"
                 : "=r"(r[0]), "=r"(r[1]), "=r"(r[2]), "=r"(r[3]) : "r"(a));
}
__device__ __forceinline__ void mma16816(float* c, const u32* a, const u32* b) {
    asm volatile("mma.sync.aligned.m16n8k16.row.col.f32.bf16.bf16.f32 "
                 "{%0,%1,%2,%3}, {%4,%5,%6,%7}, {%8,%9}, {%0,%1,%2,%3};"
                 : "+f"(c[0]), "+f"(c[1]), "+f"(c[2]), "+f"(c[3])
                 : "r"(a[0]), "r"(a[1]), "r"(a[2]), "r"(a[3]), "r"(b[0]), "r"(b[1]));
}
__device__ __forceinline__ void bsplit(float v, __nv_bfloat16& hi, __nv_bfloat16& lo) {
    hi = __float2bfloat16(v);
    lo = __float2bfloat16(v - __bfloat162float(hi));
}

// ---------------- init: zero deg/cnt + detect + weight split -----------------
__global__ void init_kernel(const int* __restrict__ src,
                            const float* __restrict__ w1, const float* __restrict__ w2) {
    int i = blockIdx.x * blockDim.x + threadIdx.x;
    if (i < N_NODES) { g_deg[i] = 0.f; g_cnt[i] = 0; }
    if (i == 0) g_sh = (src[1] == 0 && src[2] == 1) ? 1 : 0;
    if (i < HID * DIM) {
        bsplit(w1[i], g_w1h[i], g_w1l[i]);
        bsplit(w2[i], g_w2h[i], g_w2l[i]);
    }
}

__global__ void deg_hist_kernel(const int* __restrict__ src, const int* __restrict__ dst) {
    int e = blockIdx.x * blockDim.x + threadIdx.x;
    if (e < N_EDGES) {
        int sh = g_sh;
        atomicAdd(&g_deg[src[(long)e << sh]], 1.0f);
        atomicAdd(&g_cnt[dst[(long)e << sh]], 1);
    }
}

__global__ void scan_a_kernel() {
    __shared__ int s[1024];
    int t = threadIdx.x;
    int i = blockIdx.x * 1024 + t;
    s[t] = (i < N_NODES) ? g_cnt[i] : 0;
    __syncthreads();
    for (int off = 512; off > 0; off >>= 1) {
        if (t < off) s[t] += s[t + off];
        __syncthreads();
    }
    if (t == 0) g_part[blockIdx.x] = s[0];
}

__global__ void scan_c_kernel() {
    __shared__ int s[1024];
    __shared__ int base_s;
    int t = threadIdx.x;
    int b = blockIdx.x;
    int i = b * 1024 + t;
    int v = (i < N_NODES) ? g_cnt[i] : 0;
    s[t] = v;
    if (t == 0) {
        int base = 0;
        for (int k = 0; k < b; k++) base += g_part[k];
        base_s = base;
    }
    __syncthreads();
    for (int off = 1; off < 1024; off <<= 1) {
        int add = (t >= off) ? s[t - off] : 0;
        __syncthreads();
        s[t] += add;
        __syncthreads();
    }
    int base = base_s;
    if (i < N_NODES) {
        int excl = base + s[t] - v;
        g_row[i] = excl;
        g_fill[i] = excl;
        if (i == N_NODES - 1) g_row[N_NODES] = base + s[t];
    }
}

__global__ void fill_kernel(const int* __restrict__ src, const int* __restrict__ dst) {
    int e = blockIdx.x * blockDim.x + threadIdx.x;
    if (e < N_EDGES) {
        int sh = g_sh;
        int s = src[(long)e << sh];
        int d = dst[(long)e << sh];
        float c = rsqrtf(g_deg[s] * g_deg[d]);
        int pos = atomicAdd(&g_fill[d], 1);
        g_csr[pos] = make_int2(s, __float_as_int(c));
    }
}

// ---------------- forward rotation -------------------------------------------
__global__ void rot_kernel(const float* __restrict__ x, const float* __restrict__ rep,
                           float* __restrict__ out) {
    int i = blockIdx.x * blockDim.x + threadIdx.x;
    int n = i >> 7;
    int t = i & 127;
    int b = t >> 4, c = (t >> 2) & 3, el = t & 3;
    float4 r = *(const float4*)(rep + (((long)n * 8 + b) * 16 + c * 4));
    const float* xb = x + (long)n * DIM + b * 16 + el;
    out[i] = r.x * xb[0] + r.y * xb[4] + r.z * xb[8] + r.w * xb[12];
}

// ---------------- gather (unroll 4, front-batched loads) ----------------------
__global__ void gather_kernel(const float* __restrict__ hin, float* __restrict__ hout) {
    int gid = blockIdx.x * blockDim.x + threadIdx.x;
    int n = gid >> 5;
    int lane = gid & 31;
    int beg = g_row[n], end = g_row[n + 1];
    float4 acc = make_float4(0.f, 0.f, 0.f, 0.f);
    int e = beg;
    for (; e + 4 <= end; e += 4) {
        int2 c0 = g_csr[e],     c1 = g_csr[e + 1];
        int2 c2 = g_csr[e + 2], c3 = g_csr[e + 3];
        float4 v0 = __ldg((const float4*)(hin + (long)c0.x * DIM + lane * 4));
        float4 v1 = __ldg((const float4*)(hin + (long)c1.x * DIM + lane * 4));
        float4 v2 = __ldg((const float4*)(hin + (long)c2.x * DIM + lane * 4));
        float4 v3 = __ldg((const float4*)(hin + (long)c3.x * DIM + lane * 4));
        float f0 = __int_as_float(c0.y), f1 = __int_as_float(c1.y);
        float f2 = __int_as_float(c2.y), f3 = __int_as_float(c3.y);
        acc.x += v0.x * f0; acc.y += v0.y * f0; acc.z += v0.z * f0; acc.w += v0.w * f0;
        acc.x += v1.x * f1; acc.y += v1.y * f1; acc.z += v1.z * f1; acc.w += v1.w * f1;
        acc.x += v2.x * f2; acc.y += v2.y * f2; acc.z += v2.z * f2; acc.w += v2.w * f2;
        acc.x += v3.x * f3; acc.y += v3.y * f3; acc.z += v3.z * f3; acc.w += v3.w * f3;
    }
    for (; e < end; e++) {
        int2 c0 = g_csr[e];
        float4 v0 = __ldg((const float4*)(hin + (long)c0.x * DIM + lane * 4));
        float f0 = __int_as_float(c0.y);
        acc.x += v0.x * f0; acc.y += v0.y * f0; acc.z += v0.z * f0; acc.w += v0.w * f0;
    }
    *(float4*)(hout + (long)n * DIM + lane * 4) = acc;
}

// ---------------- fused FFN (HMMA): out = (gelu(rot_t(h)@w1^T+b1))@w2^T+b2 ----
// CTA: 64 nodes, both layers. Layer1: warp = 16 nodes x 128 j (jh = wid>>2).
// hid (gelu'd, bf16 hi/lo) kept in smem; layer2 warp = 16 nodes x 64 j.
// Region A: layer1 A tile (hi/lo, P1=136) then hid tile (hi/lo, P2=264).
// Region B: w1 32-k chunks (PB1=40) then w2 64-k chunks (PB2=72).
#define P1   136
#define PB1  40
#define P2   264
#define PB2  72
#define RA_SZ (64 * P2 * 2 * 2)                    // 67,584 B (hid tile is max)
#define A1_HI 0
#define A1_LO (64 * P1 * 2)                        // 17,408
#define H_HI  0
#define H_LO  (64 * P2 * 2)                        // 33,792
#define RB    RA_SZ
#define B1_HI (RB)
#define B1_LO (RB + 256 * PB1 * 2)                 // +20,480
#define B2_HI (RB)
#define B2_LO (RB + 128 * PB2 * 2)                 // +18,432
#define FF_SMEM (RA_SZ + 2 * 256 * PB1 * 2)        // 108,544 B
__global__ void __launch_bounds__(256, 2) ffn_fused(const float* __restrict__ rep,
                                                    const float* __restrict__ b1,
                                                    const float* __restrict__ b2,
                                                    float* __restrict__ out) {
    extern __shared__ char smem[];
    u32 sb = smem_u32(smem);
    int tid = threadIdx.x;
    int wid = tid >> 5, lane = tid & 31;
    int wg = wid & 3, jh = wid >> 2;
    long nbase = (long)blockIdx.x * 64;

    // ---- stage A1: rot_t(g_ha) split to hi/lo (64 rows, full K=128) ----
    for (int idx = tid; idx < 64 * 16; idx += 256) {
        int row = idx >> 4, u = idx & 15;
        long n = nbase + row; if (n >= N_NODES) n = N_NODES - 1;
        int b = u >> 1;
        const float4* hv = (const float4*)(g_ha + n * DIM + b * 16);
        float4 q0 = hv[0], q1 = hv[1], q2 = hv[2], q3 = hv[3];
        const float4* rv = (const float4*)(rep + ((long)n * 8 + b) * 16);
        float4 R0 = rv[0], R1 = rv[1], R2 = rv[2], R3 = rv[3];
        float rc[2][4];
        if (u & 1) {
            rc[0][0] = R0.z; rc[0][1] = R1.z; rc[0][2] = R2.z; rc[0][3] = R3.z;
            rc[1][0] = R0.w; rc[1][1] = R1.w; rc[1][2] = R2.w; rc[1][3] = R3.w;
        } else {
            rc[0][0] = R0.x; rc[0][1] = R1.x; rc[0][2] = R2.x; rc[0][3] = R3.x;
            rc[1][0] = R0.y; rc[1][1] = R1.y; rc[1][2] = R2.y; rc[1][3] = R3.y;
        }
        __nv_bfloat16 hi[8], lo[8];
#pragma unroll
        for (int cc = 0; cc < 2; cc++) {
            float v0 = rc[cc][0] * q0.x + rc[cc][1] * q1.x + rc[cc][2] * q2.x + rc[cc][3] * q3.x;
            float v1 = rc[cc][0] * q0.y + rc[cc][1] * q1.y + rc[cc][2] * q2.y + rc[cc][3] * q3.y;
            float v2 = rc[cc][0] * q0.z + rc[cc][1] * q1.z + rc[cc][2] * q2.z + rc[cc][3] * q3.z;
            float v3 = rc[cc][0] * q0.w + rc[cc][1] * q1.w + rc[cc][2] * q2.w + rc[cc][3] * q3.w;
            bsplit(v0, hi[cc * 4 + 0], lo[cc * 4 + 0]);
            bsplit(v1, hi[cc * 4 + 1], lo[cc * 4 + 1]);
            bsplit(v2, hi[cc * 4 + 2], lo[cc * 4 + 2]);
            bsplit(v3, hi[cc * 4 + 3], lo[cc * 4 + 3]);
        }
        *(uint4*)(smem + A1_HI + (row * P1 + u * 8) * 2) = *(uint4*)hi;
        *(uint4*)(smem + A1_LO + (row * P1 + u * 8) * 2) = *(uint4*)lo;
    }

    // ---- layer 1 MMAs: 4 chunks of K=32 ----
    u32 a_row = (u32)(wg * 16 + (lane & 15));
    u32 a_col = (u32)((lane >> 4) * 8);
    u32 aH = sb + A1_HI + (a_row * P1 + a_col) * 2;
    u32 aL = sb + A1_LO + (a_row * P1 + a_col) * 2;
    int g = lane >> 3;
    u32 brow = (u32)(jh * 128 + (g >> 1) * 8 + (lane & 7));
    u32 bcol = (u32)((g & 1) * 8);
    u32 bH4 = sb + B1_HI + (brow * PB1 + bcol) * 2;
    u32 bL4 = sb + B1_LO + (brow * PB1 + bcol) * 2;

    float acc[16][4];
#pragma unroll
    for (int t = 0; t < 16; t++)
#pragma unroll
        for (int q = 0; q < 4; q++) acc[t][q] = 0.f;

#pragma unroll
    for (int kc = 0; kc < 4; kc++) {
        // stage w1 chunk: 256 j-rows x 32 k
        for (int idx = tid; idx < 256 * 4; idx += 256) {
            int row = idx >> 2, u = idx & 3;
            long koff = kc * 32 + u * 8;
            *(uint4*)(smem + B1_HI + (row * PB1 + u * 8) * 2) = *(const uint4*)(g_w1h + (long)row * DIM + koff);
            *(uint4*)(smem + B1_LO + (row * PB1 + u * 8) * 2) = *(const uint4*)(g_w1l + (long)row * DIM + koff);
        }
        __syncthreads();
#pragma unroll
        for (int ks = 0; ks < 2; ks++) {
            u32 ah[4], al[4];
            ldsm4(ah, aH + kc * 64 + ks * 32);
            ldsm4(al, aL + kc * 64 + ks * 32);
#pragma unroll
            for (int jp = 0; jp < 8; jp++) {
                u32 bh[4], bl[4];
                ldsm4(bh, bH4 + jp * (16 * PB1 * 2) + ks * 32);
                ldsm4(bl, bL4 + jp * (16 * PB1 * 2) + ks * 32);
                mma16816(acc[2 * jp],     ah, &bh[0]);
                mma16816(acc[2 * jp],     ah, &bl[0]);
                mma16816(acc[2 * jp],     al, &bh[0]);
                mma16816(acc[2 * jp + 1], ah, &bh[2]);
                mma16816(acc[2 * jp + 1], ah, &bl[2]);
                mma16816(acc[2 * jp + 1], al, &bh[2]);
            }
        }
        __syncthreads();
    }

    // ---- layer 1 epilogue: bias + GELU, split, write hid tile to smem ----
    {
        int r0 = wg * 16 + (lane >> 2);
        int r1 = r0 + 8;
#pragma unroll
        for (int jt = 0; jt < 16; jt++) {
            int jg = jh * 128 + jt * 8 + (lane & 3) * 2;
            float bj0 = __ldg(&b1[jg]), bj1 = __ldg(&b1[jg + 1]);
#pragma unroll
            for (int half = 0; half < 2; half++) {
                int r = half ? r1 : r0;
                float a0 = acc[jt][half * 2 + 0] + bj0;
                float a1 = acc[jt][half * 2 + 1] + bj1;
                float y0 = 0.5f * a0 * (1.0f + erff(a0 * 0.7071067811865476f));
                float y1 = 0.5f * a1 * (1.0f + erff(a1 * 0.7071067811865476f));
                __nv_bfloat162 ph, pl;
                bsplit(y0, ph.x, pl.x);
                bsplit(y1, ph.y, pl.y);
                *(u32*)(smem + H_HI + (r * P2 + jg) * 2) = *(u32*)&ph;
                *(u32*)(smem + H_LO + (r * P2 + jg) * 2) = *(u32*)&pl;
            }
        }
    }
    __syncthreads();

    // ---- layer 2 MMAs: 4 chunks of K=64; warp = 16 nodes x 64 j ----
    u32 aH2 = sb + H_HI + (a_row * P2 + a_col) * 2;
    u32 aL2 = sb + H_LO + (a_row * P2 + a_col) * 2;
    u32 brow2 = (u32)(jh * 64 + (g >> 1) * 8 + (lane & 7));
    u32 bH2 = sb + B2_HI + (brow2 * PB2 + bcol) * 2;
    u32 bL2 = sb + B2_LO + (brow2 * PB2 + bcol) * 2;

    float acc2[8][4];
#pragma unroll
    for (int t = 0; t < 8; t++)
#pragma unroll
        for (int q = 0; q < 4; q++) acc2[t][q] = 0.f;

#pragma unroll
    for (int kc = 0; kc < 4; kc++) {
        // stage w2 chunk: 128 j-rows x 64 k
        for (int idx = tid; idx < 128 * 8; idx += 256) {
            int row = idx >> 3, u = idx & 7;
            long koff = kc * 64 + u * 8;
            *(uint4*)(smem + B2_HI + (row * PB2 + u * 8) * 2) = *(const uint4*)(g_w2h + (long)row * HID + koff);
            *(uint4*)(smem + B2_LO + (row * PB2 + u * 8) * 2) = *(const uint4*)(g_w2l + (long)row * HID + koff);
        }
        __syncthreads();
#pragma unroll
        for (int ks = 0; ks < 4; ks++) {
            u32 ah[4], al[4];
            ldsm4(ah, aH2 + kc * 128 + ks * 32);
            ldsm4(al, aL2 + kc * 128 + ks * 32);
#pragma unroll
            for (int jp = 0; jp < 4; jp++) {
                u32 bh[4], bl[4];
                ldsm4(bh, bH2 + jp * (16 * PB2 * 2) + ks * 32);
                ldsm4(bl, bL2 + jp * (16 * PB2 * 2) + ks * 32);
                mma16816(acc2[2 * jp],     ah, &bh[0]);
                mma16816(acc2[2 * jp],     ah, &bl[0]);
                mma16816(acc2[2 * jp],     al, &bh[0]);
                mma16816(acc2[2 * jp + 1], ah, &bh[2]);
                mma16816(acc2[2 * jp + 1], ah, &bl[2]);
                mma16816(acc2[2 * jp + 1], al, &bh[2]);
            }
        }
        __syncthreads();
    }

    // ---- layer 2 epilogue: bias, store out ----
    long n0 = nbase + wg * 16 + (lane >> 2);
    long n1 = n0 + 8;
#pragma unroll
    for (int jt = 0; jt < 8; jt++) {
        int jg = jh * 64 + jt * 8 + (lane & 3) * 2;
        float bj0 = __ldg(&b2[jg]), bj1 = __ldg(&b2[jg + 1]);
        if (n0 < N_NODES) {
            float2 v = make_float2(acc2[jt][0] + bj0, acc2[jt][1] + bj1);
            *(float2*)(out + n0 * DIM + jg) = v;
        }
        if (n1 < N_NODES) {
            float2 v = make_float2(acc2[jt][2] + bj0, acc2[jt][3] + bj1);
            *(float2*)(out + n1 * DIM + jg) = v;
        }
    }
}

// ---------------- launch ----------------------------------------------------
extern "C" void kernel_launch(void* const* d_in, const int* in_sizes, int n_in,
                              void* d_out, int out_size) {
    const float* x   = (const float*)d_in[0];
    const float* rep = (const float*)d_in[1];
    const int*   src = (const int*)d_in[2];
    const int*   dst = (const int*)d_in[3];
    const float* w1  = (const float*)d_in[4];
    const float* b1  = (const float*)d_in[5];
    const float* w2  = (const float*)d_in[6];
    const float* b2  = (const float*)d_in[7];
    float* out = (float*)d_out;

    static int smem_set = 0;
    if (!smem_set) {
        cudaFuncSetAttribute(ffn_fused, cudaFuncAttributeMaxDynamicSharedMemorySize, FF_SMEM);
        smem_set = 1;
    }

    float *ha, *hb;
    cudaGetSymbolAddress((void**)&ha, g_ha);
    cudaGetSymbolAddress((void**)&hb, g_hb);

    // CSR build (+ weight split fused into init)
    init_kernel<<<(N_NODES + 255) / 256, 256>>>(src, w1, w2);
    deg_hist_kernel<<<N_EDGES / 256, 256>>>(src, dst);
    scan_a_kernel<<<SCAN_B, 1024>>>();
    scan_c_kernel<<<SCAN_B, 1024>>>();
    fill_kernel<<<N_EDGES / 256, 256>>>(src, dst);

    // forward rotation x -> ha
    rot_kernel<<<(N_NODES * DIM) / 256, 256>>>(x, rep, ha);

    // message passing: ha -> hb -> ha
    gather_kernel<<<(N_NODES * 32) / 256, 256>>>(ha, hb);
    gather_kernel<<<(N_NODES * 32) / 256, 256>>>(hb, ha);

    // fused FFN (rot_t + layer1 + gelu + layer2, hid never leaves smem)
    ffn_fused<<<(N_NODES + 63) / 64, 256, FF_SMEM>>>(rep, b1, b2, out);
}